// round 3
// baseline (speedup 1.0000x reference)
#include <cuda_runtime.h>
#include <math.h>

#define SS   4096
#define DM   1024
#define HH   16
#define DKK  64
#define GG   1
#define NNG  (SS - 2*GG)     // 4094
#define KSEL 32
#define SCALE 0.125f         // 1/sqrt(64)

// Scratch (device globals — no allocation allowed)
__device__ float g_q[SS*DM];
__device__ float g_k[SS*DM];
__device__ float g_v[SS*DM];
__device__ float g_o[SS*DM];
__device__ int   g_sel[NNG*KSEL];

// ---------------------------------------------------------------------------
// Decode idx buffer (int64 or int32, sniffed from element layout).
// idx[0][1] is randint in [1, S) so it is never 0. If the second 32-bit word
// of the buffer is 0, the buffer must be int64 (high word of value < 4096).
// ---------------------------------------------------------------------------
__global__ void decode_idx(const void* __restrict__ raw) {
    int i = blockIdx.x * blockDim.x + threadIdx.x;
    if (i >= NNG * KSEL) return;
    const int* p32 = (const int*)raw;
    int v;
    if (p32[1] == 0) {
        v = (int)((const long long*)raw)[i];
    } else {
        v = p32[i];
    }
    g_sel[i] = v;
}

// ---------------------------------------------------------------------------
// SGEMM: C[M,N] = A[M,K] * B[K,N], all row-major fp32.
// 128x128 block tile, BK=16, 8x8 per-thread microtile, 256 threads.
// Dims assumed divisible by tile sizes (4096/1024 -> yes).
// ---------------------------------------------------------------------------
__global__ __launch_bounds__(256, 2)
void sgemm128(const float* __restrict__ A, const float* __restrict__ B,
              float* __restrict__ C, int M, int N, int K) {
    __shared__ float As[16][128];
    __shared__ float Bs[16][128];

    const int tid = threadIdx.x;
    const int tx  = tid & 15;       // 0..15 -> N dir
    const int ty  = tid >> 4;       // 0..15 -> M dir
    const int bx  = blockIdx.x;     // N tile
    const int by  = blockIdx.y;     // M tile

    const float* Ab = A + (size_t)by * 128 * K;
    const float* Bb = B + (size_t)bx * 128;

    float acc[8][8];
#pragma unroll
    for (int i = 0; i < 8; i++)
#pragma unroll
        for (int j = 0; j < 8; j++) acc[i][j] = 0.0f;

    // A tile: 128 rows x 16 cols = 512 float4; 2 per thread
    const int ar0 = tid >> 2;              // row 0..63
    const int ar1 = (tid + 256) >> 2;      // row 64..127
    const int ac  = (tid & 3) * 4;         // col 0,4,8,12
    // B tile: 16 rows x 128 cols = 512 float4; 2 per thread
    const int br0 = tid >> 5;              // row 0..7
    const int br1 = (tid + 256) >> 5;      // row 8..15
    const int bc  = (tid & 31) * 4;        // col 0..124

    for (int kt = 0; kt < K; kt += 16) {
        float4 a0 = *(const float4*)(Ab + (size_t)ar0 * K + kt + ac);
        float4 a1 = *(const float4*)(Ab + (size_t)ar1 * K + kt + ac);
        float4 b0 = *(const float4*)(Bb + (size_t)(kt + br0) * N + bc);
        float4 b1 = *(const float4*)(Bb + (size_t)(kt + br1) * N + bc);

        As[ac + 0][ar0] = a0.x; As[ac + 1][ar0] = a0.y;
        As[ac + 2][ar0] = a0.z; As[ac + 3][ar0] = a0.w;
        As[ac + 0][ar1] = a1.x; As[ac + 1][ar1] = a1.y;
        As[ac + 2][ar1] = a1.z; As[ac + 3][ar1] = a1.w;
        *(float4*)&Bs[br0][bc] = b0;
        *(float4*)&Bs[br1][bc] = b1;
        __syncthreads();

#pragma unroll
        for (int kk = 0; kk < 16; kk++) {
            float a[8], b[8];
            *(float4*)(a)     = *(const float4*)&As[kk][ty * 8];
            *(float4*)(a + 4) = *(const float4*)&As[kk][ty * 8 + 4];
            *(float4*)(b)     = *(const float4*)&Bs[kk][tx * 8];
            *(float4*)(b + 4) = *(const float4*)&Bs[kk][tx * 8 + 4];
#pragma unroll
            for (int i = 0; i < 8; i++)
#pragma unroll
                for (int j = 0; j < 8; j++)
                    acc[i][j] = fmaf(a[i], b[j], acc[i][j]);
        }
        __syncthreads();
    }

    float* Cb = C + (size_t)(by * 128 + ty * 8) * N + bx * 128 + tx * 8;
#pragma unroll
    for (int i = 0; i < 8; i++) {
        *(float4*)(Cb + (size_t)i * N)     = make_float4(acc[i][0], acc[i][1], acc[i][2], acc[i][3]);
        *(float4*)(Cb + (size_t)i * N + 4) = make_float4(acc[i][4], acc[i][5], acc[i][6], acc[i][7]);
    }
}

// ---------------------------------------------------------------------------
// Sparse attention: one warp per (token, head). 32 lanes = 32 selected keys.
// q/k/v stored (S, H*64) so a head slice of a key row is 256B contiguous.
// ---------------------------------------------------------------------------
__global__ __launch_bounds__(128)
void sparse_attn() {
    const int warp = blockIdx.x * 4 + (threadIdx.x >> 5);
    const int lane = threadIdx.x & 31;
    const int t = warp >> 4;     // token index in [0, NNG)
    const int h = warp & 15;     // head

    const int kidx = g_sel[t * KSEL + lane];
    const float4* krow = (const float4*)(g_k + (size_t)kidx * DM + h * DKK);
    const float4* qrow = (const float4*)(g_q + (size_t)(t + GG) * DM + h * DKK);

    float dot = 0.0f;
#pragma unroll
    for (int i = 0; i < 16; i++) {
        float4 kv = krow[i], qv = qrow[i];
        dot = fmaf(kv.x, qv.x, dot);
        dot = fmaf(kv.y, qv.y, dot);
        dot = fmaf(kv.z, qv.z, dot);
        dot = fmaf(kv.w, qv.w, dot);
    }
    float lg = dot * SCALE;

    float m = lg;
#pragma unroll
    for (int o = 16; o; o >>= 1) m = fmaxf(m, __shfl_xor_sync(0xffffffffu, m, o));
    float e = __expf(lg - m);
    float sum = e;
#pragma unroll
    for (int o = 16; o; o >>= 1) sum += __shfl_xor_sync(0xffffffffu, sum, o);
    float p = e / sum;

    // PV: lane owns output dims (lane) and (lane+32)
    float acc0 = 0.0f, acc1 = 0.0f;
#pragma unroll
    for (int j = 0; j < 32; j++) {
        float pj = __shfl_sync(0xffffffffu, p, j);
        int   kj = __shfl_sync(0xffffffffu, kidx, j);
        const float* vrow = g_v + (size_t)kj * DM + h * DKK;
        acc0 = fmaf(pj, vrow[lane],      acc0);
        acc1 = fmaf(pj, vrow[lane + 32], acc1);
    }
    float* orow = g_o + (size_t)(t + GG) * DM + h * DKK;
    orow[lane]      = acc0;
    orow[lane + 32] = acc1;
}

// ---------------------------------------------------------------------------
// Global attention: 2*H blocks, 256 threads. Full softmax over S keys.
// ---------------------------------------------------------------------------
__global__ __launch_bounds__(256)
void global_attn() {
    __shared__ float lg[SS];
    __shared__ float red[256];
    __shared__ float ored[4][DKK];
    __shared__ __align__(16) float qs[DKK];

    const int gi = blockIdx.x >> 4;     // 0 or 1
    const int h  = blockIdx.x & 15;
    const int srow = gi ? (SS - 1) : 0;
    const int tid = threadIdx.x;

    if (tid < DKK) qs[tid] = g_q[(size_t)srow * DM + h * DKK + tid];
    __syncthreads();

    float lmax = -1e30f;
    for (int n = tid; n < SS; n += 256) {
        const float4* kr = (const float4*)(g_k + (size_t)n * DM + h * DKK);
        const float4* qr = (const float4*)qs;
        float dot = 0.0f;
#pragma unroll
        for (int i = 0; i < 16; i++) {
            float4 kv = kr[i], qv = qr[i];
            dot = fmaf(kv.x, qv.x, dot);
            dot = fmaf(kv.y, qv.y, dot);
            dot = fmaf(kv.z, qv.z, dot);
            dot = fmaf(kv.w, qv.w, dot);
        }
        float l = dot * SCALE;
        lg[n] = l;
        lmax = fmaxf(lmax, l);
    }
    red[tid] = lmax; __syncthreads();
    for (int st = 128; st; st >>= 1) {
        if (tid < st) red[tid] = fmaxf(red[tid], red[tid + st]);
        __syncthreads();
    }
    float m = red[0];
    __syncthreads();

    float lsum = 0.0f;
    for (int n = tid; n < SS; n += 256) {
        float e = __expf(lg[n] - m);
        lg[n] = e;
        lsum += e;
    }
    red[tid] = lsum; __syncthreads();
    for (int st = 128; st; st >>= 1) {
        if (tid < st) red[tid] += red[tid + st];
        __syncthreads();
    }
    float inv = 1.0f / red[0];
    __syncthreads();

    // PV: thread (c, d) with d = tid&63 accumulates quarter c of the keys
    const int d = tid & 63;
    const int c = tid >> 6;
    float acc = 0.0f;
    const float* vb = g_v + h * DKK + d;
    const int n0 = c * (SS / 4), n1 = n0 + (SS / 4);
    for (int n = n0; n < n1; n++)
        acc = fmaf(lg[n], vb[(size_t)n * DM], acc);
    ored[c][d] = acc;
    __syncthreads();

    if (tid < DKK) {
        g_o[(size_t)srow * DM + h * DKK + tid] =
            (ored[0][tid] + ored[1][tid] + ored[2][tid] + ored[3][tid]) * inv;
    }
}

// ---------------------------------------------------------------------------
extern "C" void kernel_launch(void* const* d_in, const int* in_sizes, int n_in,
                              void* d_out, int out_size) {
    const float* Q  = (const float*)d_in[0];
    const float* Kk = (const float*)d_in[1];
    const float* V  = (const float*)d_in[2];
    const float* Wq = (const float*)d_in[3];
    const float* Wk = (const float*)d_in[4];
    const float* Wv = (const float*)d_in[5];
    const float* Wo = (const float*)d_in[6];
    const void*  idx = (const void*)d_in[7];
    float* out = (float*)d_out;

    float *pq, *pk, *pv, *po;
    cudaGetSymbolAddress((void**)&pq, g_q);
    cudaGetSymbolAddress((void**)&pk, g_k);
    cudaGetSymbolAddress((void**)&pv, g_v);
    cudaGetSymbolAddress((void**)&po, g_o);

    decode_idx<<<(NNG * KSEL + 255) / 256, 256>>>(idx);

    dim3 gemm_grid(DM / 128, SS / 128);   // (8, 32)
    sgemm128<<<gemm_grid, 256>>>(Q,  Wq, pq, SS, DM, DM);
    sgemm128<<<gemm_grid, 256>>>(Kk, Wk, pk, SS, DM, DM);
    sgemm128<<<gemm_grid, 256>>>(V,  Wv, pv, SS, DM, DM);

    sparse_attn<<<(NNG * HH) / 4, 128>>>();
    global_attn<<<2 * HH, 256>>>();

    sgemm128<<<gemm_grid, 256>>>(po, Wo, out, SS, DM, DM);
}

// round 4
// speedup vs baseline: 1.1540x; 1.1540x over previous
#include <cuda_runtime.h>
#include <math.h>

#define SS   4096
#define DM   1024
#define HH   16
#define DKK  64
#define GG   1
#define NNG  (SS - 2*GG)     // 4094
#define KSEL 32
#define SCALE 0.125f         // 1/sqrt(64)

// Scratch (device globals — no allocation allowed)
__device__ float g_q[SS*DM];
__device__ float g_k[SS*DM];
__device__ float g_v[SS*DM];
__device__ float g_o[SS*DM];
__device__ int   g_sel[NNG*KSEL];

// ---------------------------------------------------------------------------
// Decode idx buffer (int64 or int32, sniffed from element layout).
// ---------------------------------------------------------------------------
__global__ void decode_idx(const void* __restrict__ raw) {
    int i = blockIdx.x * blockDim.x + threadIdx.x;
    if (i >= NNG * KSEL) return;
    const int* p32 = (const int*)raw;
    int v;
    if (p32[1] == 0) {
        v = (int)((const long long*)raw)[i];
    } else {
        v = p32[i];
    }
    g_sel[i] = v;
}

// ---------------------------------------------------------------------------
// TF32 tensor-core GEMM: C[M,N] = A[M,K] * B[K,N], row-major fp32 in/out.
// 128x128 block tile, BK=16, 8 warps (4 M x 2 N), warp tile 32x64.
// mma.sync.aligned.m16n8k8.row.col.f32.tf32.tf32.f32
// Double-buffered smem with register-staged global prefetch.
// ---------------------------------------------------------------------------
#define BM 128
#define BN 128
#define BK 16
#define SPAD 4
#define SSTRIDE (BM + SPAD)   // 132

__device__ __forceinline__ float to_tf32(float x) {
    unsigned r;
    asm("cvt.rna.tf32.f32 %0, %1;" : "=r"(r) : "f"(x));
    return __uint_as_float(r);
}

__device__ __forceinline__ void mma_tf32(float& c0, float& c1, float& c2, float& c3,
                                         unsigned a0, unsigned a1, unsigned a2, unsigned a3,
                                         unsigned b0, unsigned b1) {
    asm volatile(
        "mma.sync.aligned.m16n8k8.row.col.f32.tf32.tf32.f32 "
        "{%0,%1,%2,%3}, {%4,%5,%6,%7}, {%8,%9}, {%0,%1,%2,%3};"
        : "+f"(c0), "+f"(c1), "+f"(c2), "+f"(c3)
        : "r"(a0), "r"(a1), "r"(a2), "r"(a3), "r"(b0), "r"(b1));
}

__global__ __launch_bounds__(256)
void sgemm_tf32(const float* __restrict__ A, const float* __restrict__ B,
                float* __restrict__ C, int M, int N, int K) {
    // As: [BK][BM+pad], k-major so A-fragment loads are conflict-free
    // Bs: [BK][BN+pad]
    __shared__ float As[2][BK][SSTRIDE];
    __shared__ float Bs[2][BK][SSTRIDE];

    const int tid  = threadIdx.x;
    const int lane = tid & 31;
    const int warp = tid >> 5;
    const int wm   = warp & 3;        // 0..3 -> M
    const int wn   = warp >> 2;       // 0..1 -> N
    const int gid  = lane >> 2;       // 0..7
    const int qid  = lane & 3;        // 0..3

    const int bx = blockIdx.x;        // N tile
    const int by = blockIdx.y;        // M tile

    const float* Ab = A + (size_t)by * BM * K;
    const float* Bb = B + (size_t)bx * BN;

    // Global-load mapping
    const int ar0 = tid >> 2;            // A rows 0..63
    const int ar1 = ar0 + 64;            // 64..127
    const int ac  = (tid & 3) * 4;       // A k-offset 0,4,8,12
    const int br0 = tid >> 5;            // B rows 0..7
    const int br1 = br0 + 8;             // 8..15
    const int bc  = (tid & 31) * 4;      // B col 0..124

    float acc[2][8][4];
#pragma unroll
    for (int mi = 0; mi < 2; mi++)
#pragma unroll
        for (int ni = 0; ni < 8; ni++)
#pragma unroll
            for (int r = 0; r < 4; r++) acc[mi][ni][r] = 0.0f;

    // --- load tile 0 into buffer 0 ---
    {
        float4 a0 = *(const float4*)(Ab + (size_t)ar0 * K + ac);
        float4 a1 = *(const float4*)(Ab + (size_t)ar1 * K + ac);
        float4 b0 = *(const float4*)(Bb + (size_t)br0 * N + bc);
        float4 b1 = *(const float4*)(Bb + (size_t)br1 * N + bc);
        As[0][ac + 0][ar0] = to_tf32(a0.x); As[0][ac + 1][ar0] = to_tf32(a0.y);
        As[0][ac + 2][ar0] = to_tf32(a0.z); As[0][ac + 3][ar0] = to_tf32(a0.w);
        As[0][ac + 0][ar1] = to_tf32(a1.x); As[0][ac + 1][ar1] = to_tf32(a1.y);
        As[0][ac + 2][ar1] = to_tf32(a1.z); As[0][ac + 3][ar1] = to_tf32(a1.w);
        Bs[0][br0][bc + 0] = to_tf32(b0.x); Bs[0][br0][bc + 1] = to_tf32(b0.y);
        Bs[0][br0][bc + 2] = to_tf32(b0.z); Bs[0][br0][bc + 3] = to_tf32(b0.w);
        Bs[0][br1][bc + 0] = to_tf32(b1.x); Bs[0][br1][bc + 1] = to_tf32(b1.y);
        Bs[0][br1][bc + 2] = to_tf32(b1.z); Bs[0][br1][bc + 3] = to_tf32(b1.w);
    }
    __syncthreads();

    const int nk = K / BK;
    float4 pa0, pa1, pb0, pb1;

    for (int kt = 0; kt < nk; kt++) {
        const int cur = kt & 1;

        // prefetch next tile into registers
        if (kt + 1 < nk) {
            const int ko = (kt + 1) * BK;
            pa0 = *(const float4*)(Ab + (size_t)ar0 * K + ko + ac);
            pa1 = *(const float4*)(Ab + (size_t)ar1 * K + ko + ac);
            pb0 = *(const float4*)(Bb + (size_t)(ko + br0) * N + bc);
            pb1 = *(const float4*)(Bb + (size_t)(ko + br1) * N + bc);
        }

        // compute on current buffer: 2 k-chunks of 8
#pragma unroll
        for (int kc = 0; kc < 2; kc++) {
            const int kk = kc * 8;
            unsigned afr[2][4], bfr[8][2];
#pragma unroll
            for (int mi = 0; mi < 2; mi++) {
                const int r0 = wm * 32 + mi * 16;
                afr[mi][0] = __float_as_uint(As[cur][kk + qid    ][r0 + gid    ]);
                afr[mi][1] = __float_as_uint(As[cur][kk + qid    ][r0 + gid + 8]);
                afr[mi][2] = __float_as_uint(As[cur][kk + qid + 4][r0 + gid    ]);
                afr[mi][3] = __float_as_uint(As[cur][kk + qid + 4][r0 + gid + 8]);
            }
#pragma unroll
            for (int ni = 0; ni < 8; ni++) {
                const int c0 = wn * 64 + ni * 8;
                bfr[ni][0] = __float_as_uint(Bs[cur][kk + qid    ][c0 + gid]);
                bfr[ni][1] = __float_as_uint(Bs[cur][kk + qid + 4][c0 + gid]);
            }
#pragma unroll
            for (int mi = 0; mi < 2; mi++)
#pragma unroll
                for (int ni = 0; ni < 8; ni++)
                    mma_tf32(acc[mi][ni][0], acc[mi][ni][1], acc[mi][ni][2], acc[mi][ni][3],
                             afr[mi][0], afr[mi][1], afr[mi][2], afr[mi][3],
                             bfr[ni][0], bfr[ni][1]);
        }

        // store prefetched tile into the other buffer
        if (kt + 1 < nk) {
            const int nxt = (kt + 1) & 1;
            As[nxt][ac + 0][ar0] = to_tf32(pa0.x); As[nxt][ac + 1][ar0] = to_tf32(pa0.y);
            As[nxt][ac + 2][ar0] = to_tf32(pa0.z); As[nxt][ac + 3][ar0] = to_tf32(pa0.w);
            As[nxt][ac + 0][ar1] = to_tf32(pa1.x); As[nxt][ac + 1][ar1] = to_tf32(pa1.y);
            As[nxt][ac + 2][ar1] = to_tf32(pa1.z); As[nxt][ac + 3][ar1] = to_tf32(pa1.w);
            Bs[nxt][br0][bc + 0] = to_tf32(pb0.x); Bs[nxt][br0][bc + 1] = to_tf32(pb0.y);
            Bs[nxt][br0][bc + 2] = to_tf32(pb0.z); Bs[nxt][br0][bc + 3] = to_tf32(pb0.w);
            Bs[nxt][br1][bc + 0] = to_tf32(pb1.x); Bs[nxt][br1][bc + 1] = to_tf32(pb1.y);
            Bs[nxt][br1][bc + 2] = to_tf32(pb1.z); Bs[nxt][br1][bc + 3] = to_tf32(pb1.w);
        }
        __syncthreads();
    }

    // epilogue: c0,c1 at (row, col..col+1), c2,c3 at (row+8, ...)
#pragma unroll
    for (int mi = 0; mi < 2; mi++) {
        const int row = by * BM + wm * 32 + mi * 16 + gid;
#pragma unroll
        for (int ni = 0; ni < 8; ni++) {
            const int col = bx * BN + wn * 64 + ni * 8 + 2 * qid;
            *(float2*)(C + (size_t)row * N + col) =
                make_float2(acc[mi][ni][0], acc[mi][ni][1]);
            *(float2*)(C + (size_t)(row + 8) * N + col) =
                make_float2(acc[mi][ni][2], acc[mi][ni][3]);
        }
    }
}

// ---------------------------------------------------------------------------
// Sparse attention: one warp per (token, head). 32 lanes = 32 selected keys.
// ---------------------------------------------------------------------------
__global__ __launch_bounds__(128)
void sparse_attn() {
    const int warp = blockIdx.x * 4 + (threadIdx.x >> 5);
    const int lane = threadIdx.x & 31;
    const int t = warp >> 4;     // token index in [0, NNG)
    const int h = warp & 15;     // head

    const int kidx = g_sel[t * KSEL + lane];
    const float4* krow = (const float4*)(g_k + (size_t)kidx * DM + h * DKK);
    const float4* qrow = (const float4*)(g_q + (size_t)(t + GG) * DM + h * DKK);

    float dot = 0.0f;
#pragma unroll
    for (int i = 0; i < 16; i++) {
        float4 kv = krow[i], qv = qrow[i];
        dot = fmaf(kv.x, qv.x, dot);
        dot = fmaf(kv.y, qv.y, dot);
        dot = fmaf(kv.z, qv.z, dot);
        dot = fmaf(kv.w, qv.w, dot);
    }
    float lg = dot * SCALE;

    float m = lg;
#pragma unroll
    for (int o = 16; o; o >>= 1) m = fmaxf(m, __shfl_xor_sync(0xffffffffu, m, o));
    float e = __expf(lg - m);
    float sum = e;
#pragma unroll
    for (int o = 16; o; o >>= 1) sum += __shfl_xor_sync(0xffffffffu, sum, o);
    float p = e / sum;

    float acc0 = 0.0f, acc1 = 0.0f;
#pragma unroll
    for (int j = 0; j < 32; j++) {
        float pj = __shfl_sync(0xffffffffu, p, j);
        int   kj = __shfl_sync(0xffffffffu, kidx, j);
        const float* vrow = g_v + (size_t)kj * DM + h * DKK;
        acc0 = fmaf(pj, vrow[lane],      acc0);
        acc1 = fmaf(pj, vrow[lane + 32], acc1);
    }
    float* orow = g_o + (size_t)(t + GG) * DM + h * DKK;
    orow[lane]      = acc0;
    orow[lane + 32] = acc1;
}

// ---------------------------------------------------------------------------
// Global attention: 2*H blocks, 256 threads. Full softmax over S keys.
// ---------------------------------------------------------------------------
__global__ __launch_bounds__(256)
void global_attn() {
    __shared__ float lg[SS];
    __shared__ float red[256];
    __shared__ float ored[4][DKK];
    __shared__ __align__(16) float qs[DKK];

    const int gi = blockIdx.x >> 4;     // 0 or 1
    const int h  = blockIdx.x & 15;
    const int srow = gi ? (SS - 1) : 0;
    const int tid = threadIdx.x;

    if (tid < DKK) qs[tid] = g_q[(size_t)srow * DM + h * DKK + tid];
    __syncthreads();

    float lmax = -1e30f;
    for (int n = tid; n < SS; n += 256) {
        const float4* kr = (const float4*)(g_k + (size_t)n * DM + h * DKK);
        const float4* qr = (const float4*)qs;
        float dot = 0.0f;
#pragma unroll
        for (int i = 0; i < 16; i++) {
            float4 kv = kr[i], qv = qr[i];
            dot = fmaf(kv.x, qv.x, dot);
            dot = fmaf(kv.y, qv.y, dot);
            dot = fmaf(kv.z, qv.z, dot);
            dot = fmaf(kv.w, qv.w, dot);
        }
        float l = dot * SCALE;
        lg[n] = l;
        lmax = fmaxf(lmax, l);
    }
    red[tid] = lmax; __syncthreads();
    for (int st = 128; st; st >>= 1) {
        if (tid < st) red[tid] = fmaxf(red[tid], red[tid + st]);
        __syncthreads();
    }
    float m = red[0];
    __syncthreads();

    float lsum = 0.0f;
    for (int n = tid; n < SS; n += 256) {
        float e = __expf(lg[n] - m);
        lg[n] = e;
        lsum += e;
    }
    red[tid] = lsum; __syncthreads();
    for (int st = 128; st; st >>= 1) {
        if (tid < st) red[tid] += red[tid + st];
        __syncthreads();
    }
    float inv = 1.0f / red[0];
    __syncthreads();

    const int d = tid & 63;
    const int c = tid >> 6;
    float acc = 0.0f;
    const float* vb = g_v + h * DKK + d;
    const int n0 = c * (SS / 4), n1 = n0 + (SS / 4);
    for (int n = n0; n < n1; n++)
        acc = fmaf(lg[n], vb[(size_t)n * DM], acc);
    ored[c][d] = acc;
    __syncthreads();

    if (tid < DKK) {
        g_o[(size_t)srow * DM + h * DKK + tid] =
            (ored[0][tid] + ored[1][tid] + ored[2][tid] + ored[3][tid]) * inv;
    }
}

// ---------------------------------------------------------------------------
extern "C" void kernel_launch(void* const* d_in, const int* in_sizes, int n_in,
                              void* d_out, int out_size) {
    const float* Q  = (const float*)d_in[0];
    const float* Kk = (const float*)d_in[1];
    const float* V  = (const float*)d_in[2];
    const float* Wq = (const float*)d_in[3];
    const float* Wk = (const float*)d_in[4];
    const float* Wv = (const float*)d_in[5];
    const float* Wo = (const float*)d_in[6];
    const void*  idx = (const void*)d_in[7];
    float* out = (float*)d_out;

    float *pq, *pk, *pv, *po;
    cudaGetSymbolAddress((void**)&pq, g_q);
    cudaGetSymbolAddress((void**)&pk, g_k);
    cudaGetSymbolAddress((void**)&pv, g_v);
    cudaGetSymbolAddress((void**)&po, g_o);

    decode_idx<<<(NNG * KSEL + 255) / 256, 256>>>(idx);

    dim3 gemm_grid(DM / 128, SS / 128);   // (8, 32)
    sgemm_tf32<<<gemm_grid, 256>>>(Q,  Wq, pq, SS, DM, DM);
    sgemm_tf32<<<gemm_grid, 256>>>(Kk, Wk, pk, SS, DM, DM);
    sgemm_tf32<<<gemm_grid, 256>>>(V,  Wv, pv, SS, DM, DM);

    sparse_attn<<<(NNG * HH) / 4, 128>>>();
    global_attn<<<2 * HH, 256>>>();

    sgemm_tf32<<<gemm_grid, 256>>>(po, Wo, out, SS, DM, DM);
}

// round 5
// speedup vs baseline: 1.2553x; 1.0878x over previous
#include <cuda_runtime.h>
#include <math.h>

#define SS   4096
#define DM   1024
#define HH   16
#define DKK  64
#define GG   1
#define NNG  (SS - 2*GG)     // 4094
#define KSEL 32
#define SCALE 0.125f         // 1/sqrt(64)

// Scratch (device globals — no allocation allowed)
__device__ float g_q[SS*DM];
__device__ float g_k[SS*DM];
__device__ float g_v[SS*DM];
__device__ float g_o[SS*DM];
__device__ int   g_sel[NNG*KSEL];

// ---------------------------------------------------------------------------
// Decode idx buffer (int64 or int32, sniffed from element layout).
// ---------------------------------------------------------------------------
__global__ void decode_idx(const void* __restrict__ raw) {
    int i = blockIdx.x * blockDim.x + threadIdx.x;
    if (i >= NNG * KSEL) return;
    const int* p32 = (const int*)raw;
    int v;
    if (p32[1] == 0) {
        v = (int)((const long long*)raw)[i];
    } else {
        v = p32[i];
    }
    g_sel[i] = v;
}

// ---------------------------------------------------------------------------
// TF32 tensor-core GEMM, k-permuted XOR-swizzled smem layout.
// C[M,N] = A[M,K]*B[K,N], row-major fp32. 128x128 tile, BK=16, 8 warps 4x2,
// warp tile 32x64. Fragments loaded via LDS.128 / LDS.64 (conflict-free).
// Element (k, x) of a tile lives at  tile[x][ ((k&3)^swz(x))*4 + (k>>2) ].
// grid.z selects one of up to 3 (A, C) pairs (fused QKV projections).
// ---------------------------------------------------------------------------
#define BM 128
#define BN 128
#define BK 16

__device__ __forceinline__ float to_tf32(float x) {
    unsigned r;
    asm("cvt.rna.tf32.f32 %0, %1;" : "=r"(r) : "f"(x));
    return __uint_as_float(r);
}
__device__ __forceinline__ int swz(int x) { return (x ^ (x >> 2)) & 3; }

__device__ __forceinline__ void mma_tf32(float& c0, float& c1, float& c2, float& c3,
                                         float a0, float a1, float a2, float a3,
                                         float b0, float b1) {
    asm volatile(
        "mma.sync.aligned.m16n8k8.row.col.f32.tf32.tf32.f32 "
        "{%0,%1,%2,%3}, {%4,%5,%6,%7}, {%8,%9}, {%0,%1,%2,%3};"
        : "+f"(c0), "+f"(c1), "+f"(c2), "+f"(c3)
        : "r"(__float_as_uint(a0)), "r"(__float_as_uint(a1)),
          "r"(__float_as_uint(a2)), "r"(__float_as_uint(a3)),
          "r"(__float_as_uint(b0)), "r"(__float_as_uint(b1)));
}

__global__ __launch_bounds__(256, 2)
void sgemm_tf32(const float* __restrict__ A0, const float* __restrict__ A1,
                const float* __restrict__ A2, const float* __restrict__ B0,
                const float* __restrict__ B1, const float* __restrict__ B2,
                float* __restrict__ C0, float* __restrict__ C1,
                float* __restrict__ C2) {
    __shared__ float As[2][BM][16];
    __shared__ float Bs[2][BN][16];

    const int K = DM, N = DM;
    const float* A = (blockIdx.z == 0) ? A0 : (blockIdx.z == 1) ? A1 : A2;
    const float* B = (blockIdx.z == 0) ? B0 : (blockIdx.z == 1) ? B1 : B2;
    float*       C = (blockIdx.z == 0) ? C0 : (blockIdx.z == 1) ? C1 : C2;

    const int tid  = threadIdx.x;
    const int lane = tid & 31;
    const int warp = tid >> 5;
    const int wm   = warp & 3;        // 0..3 -> M
    const int wn   = warp >> 2;       // 0..1 -> N
    const int gid  = lane >> 2;       // 0..7
    const int qid  = lane & 3;        // 0..3
    const int t3   = tid & 3;

    const int bx = blockIdx.x;        // N tile
    const int by = blockIdx.y;        // M tile

    const float* Ab = A + (size_t)by * BM * K;
    const float* Bb = B + (size_t)bx * BN;

    // Global-load mapping
    const int ar0 = tid >> 2;            // A rows 0..63
    const int ar1 = ar0 + 64;            // 64..127
    const int ac  = t3 * 4;              // A k-offset 0,4,8,12
    const int br0 = tid >> 5;            // B k-rows 0..7
    const int br1 = br0 + 8;             // 8..15
    const int bc  = (tid & 31) * 4;      // B col 0..124

    // Precomputed store positions
    const int sa0 = swz(ar0), sa1 = swz(ar1);

    // Precomputed fragment addresses (float index within a buffer)
    // A rows for this thread: wm*32 + {0,8,16,24} + gid
    int arow[4], aoff[4];
#pragma unroll
    for (int i = 0; i < 4; i++) {
        arow[i] = wm * 32 + i * 8 + gid;
        aoff[i] = arow[i] * 16 + ((qid ^ swz(arow[i])) << 2);
    }
    int boff[8];
#pragma unroll
    for (int ni = 0; ni < 8; ni++) {
        int n = wn * 64 + ni * 8 + gid;
        boff[ni] = n * 16 + ((qid ^ swz(n)) << 2);
    }

    float acc[2][8][4];
#pragma unroll
    for (int mi = 0; mi < 2; mi++)
#pragma unroll
        for (int ni = 0; ni < 8; ni++)
#pragma unroll
            for (int r = 0; r < 4; r++) acc[mi][ni][r] = 0.0f;

    // --- load tile 0 into buffer 0 ---
    {
        float4 a0 = *(const float4*)(Ab + (size_t)ar0 * K + ac);
        float4 a1 = *(const float4*)(Ab + (size_t)ar1 * K + ac);
        float4 b0 = *(const float4*)(Bb + (size_t)br0 * N + bc);
        float4 b1 = *(const float4*)(Bb + (size_t)br1 * N + bc);
        float av0[4] = {a0.x, a0.y, a0.z, a0.w};
        float av1[4] = {a1.x, a1.y, a1.z, a1.w};
        float bv0[4] = {b0.x, b0.y, b0.z, b0.w};
        float bv1[4] = {b1.x, b1.y, b1.z, b1.w};
#pragma unroll
        for (int j = 0; j < 4; j++) {
            As[0][ar0][((j ^ sa0) << 2) + t3] = to_tf32(av0[j]);
            As[0][ar1][((j ^ sa1) << 2) + t3] = to_tf32(av1[j]);
            Bs[0][bc + j][(((br0 & 3) ^ j ^ t3) << 2) + (br0 >> 2)] = to_tf32(bv0[j]);
            Bs[0][bc + j][(((br1 & 3) ^ j ^ t3) << 2) + (br1 >> 2)] = to_tf32(bv1[j]);
        }
    }
    __syncthreads();

    const int nk = K / BK;
    float4 pa0, pa1, pb0, pb1;

    for (int kt = 0; kt < nk; kt++) {
        const int cur = kt & 1;

        // prefetch next tile into registers
        if (kt + 1 < nk) {
            const int ko = (kt + 1) * BK;
            pa0 = *(const float4*)(Ab + (size_t)ar0 * K + ko + ac);
            pa1 = *(const float4*)(Ab + (size_t)ar1 * K + ko + ac);
            pb0 = *(const float4*)(Bb + (size_t)(ko + br0) * N + bc);
            pb1 = *(const float4*)(Bb + (size_t)(ko + br1) * N + bc);
        }

        // A fragments: one LDS.128 per row covers all 16 k
        float4 av[4];
        {
            const float* base = &As[cur][0][0];
#pragma unroll
            for (int i = 0; i < 4; i++)
                av[i] = *(const float4*)(base + aoff[i]);
        }

        // two k-chunks of 8
#pragma unroll
        for (int kc = 0; kc < 2; kc++) {
            float2 bv[8];
            {
                const float* base = &Bs[cur][0][0] + kc * 2;
#pragma unroll
                for (int ni = 0; ni < 8; ni++)
                    bv[ni] = *(const float2*)(base + boff[ni]);
            }
#pragma unroll
            for (int mi = 0; mi < 2; mi++) {
                const float4 lo = av[mi * 2];
                const float4 hi = av[mi * 2 + 1];
                const float a0 = kc ? lo.z : lo.x;
                const float a1 = kc ? hi.z : hi.x;
                const float a2 = kc ? lo.w : lo.y;
                const float a3 = kc ? hi.w : hi.y;
#pragma unroll
                for (int ni = 0; ni < 8; ni++)
                    mma_tf32(acc[mi][ni][0], acc[mi][ni][1], acc[mi][ni][2], acc[mi][ni][3],
                             a0, a1, a2, a3, bv[ni].x, bv[ni].y);
            }
        }

        // store prefetched tile into the other buffer
        if (kt + 1 < nk) {
            const int nxt = (kt + 1) & 1;
            float av0[4] = {pa0.x, pa0.y, pa0.z, pa0.w};
            float av1[4] = {pa1.x, pa1.y, pa1.z, pa1.w};
            float bv0[4] = {pb0.x, pb0.y, pb0.z, pb0.w};
            float bv1[4] = {pb1.x, pb1.y, pb1.z, pb1.w};
#pragma unroll
            for (int j = 0; j < 4; j++) {
                As[nxt][ar0][((j ^ sa0) << 2) + t3] = to_tf32(av0[j]);
                As[nxt][ar1][((j ^ sa1) << 2) + t3] = to_tf32(av1[j]);
                Bs[nxt][bc + j][(((br0 & 3) ^ j ^ t3) << 2) + (br0 >> 2)] = to_tf32(bv0[j]);
                Bs[nxt][bc + j][(((br1 & 3) ^ j ^ t3) << 2) + (br1 >> 2)] = to_tf32(bv1[j]);
            }
        }
        __syncthreads();
    }

    // epilogue
#pragma unroll
    for (int mi = 0; mi < 2; mi++) {
        const int row = by * BM + wm * 32 + mi * 16 + gid;
#pragma unroll
        for (int ni = 0; ni < 8; ni++) {
            const int col = bx * BN + wn * 64 + ni * 8 + 2 * qid;
            *(float2*)(C + (size_t)row * N + col) =
                make_float2(acc[mi][ni][0], acc[mi][ni][1]);
            *(float2*)(C + (size_t)(row + 8) * N + col) =
                make_float2(acc[mi][ni][2], acc[mi][ni][3]);
        }
    }
}

// ---------------------------------------------------------------------------
// Sparse attention: one warp per (token, head).
// QK via coalesced cooperative loads + butterfly transpose-reduce.
// ---------------------------------------------------------------------------
__global__ __launch_bounds__(128)
void sparse_attn() {
    const int warp = blockIdx.x * 4 + (threadIdx.x >> 5);
    const int lane = threadIdx.x & 31;
    const int t = warp >> 4;     // token index in [0, NNG)
    const int h = warp & 15;     // head

    const int kidx = g_sel[t * KSEL + lane];

    // lane holds dims (2*lane, 2*lane+1) of q
    const float2 qv = *(const float2*)(g_q + (size_t)(t + GG) * DM + h * DKK + lane * 2);

    // partial dot for each of 32 keys
    float p[32];
#pragma unroll
    for (int j = 0; j < 32; j++) {
        const int kj = __shfl_sync(0xffffffffu, kidx, j);
        const float2 kv = *(const float2*)(g_k + (size_t)kj * DM + h * DKK + lane * 2);
        p[j] = qv.x * kv.x + qv.y * kv.y;
    }

    // butterfly transpose-reduce: afterwards p[0] on lane L = full dot for key L
#pragma unroll
    for (int o = 16; o; o >>= 1) {
#pragma unroll
        for (int j = 0; j < o; j++) {
            const bool up = (lane & o) != 0;
            const float mine  = up ? p[j + o] : p[j];
            const float other = up ? p[j]     : p[j + o];
            p[j] = mine + __shfl_xor_sync(0xffffffffu, other, o);
        }
    }
    const float lg = p[0] * SCALE;

    float m = lg;
#pragma unroll
    for (int o = 16; o; o >>= 1) m = fmaxf(m, __shfl_xor_sync(0xffffffffu, m, o));
    float e = __expf(lg - m);
    float sum = e;
#pragma unroll
    for (int o = 16; o; o >>= 1) sum += __shfl_xor_sync(0xffffffffu, sum, o);
    const float prob = e / sum;

    // PV: lane owns output dims (lane) and (lane+32); coalesced V loads
    float acc0 = 0.0f, acc1 = 0.0f;
#pragma unroll
    for (int j = 0; j < 32; j++) {
        const float pj = __shfl_sync(0xffffffffu, prob, j);
        const int   kj = __shfl_sync(0xffffffffu, kidx, j);
        const float* vrow = g_v + (size_t)kj * DM + h * DKK;
        acc0 = fmaf(pj, vrow[lane],      acc0);
        acc1 = fmaf(pj, vrow[lane + 32], acc1);
    }
    float* orow = g_o + (size_t)(t + GG) * DM + h * DKK;
    orow[lane]      = acc0;
    orow[lane + 32] = acc1;
}

// ---------------------------------------------------------------------------
// Global attention: 2*H blocks, 256 threads. Full softmax over S keys.
// ---------------------------------------------------------------------------
__global__ __launch_bounds__(256)
void global_attn() {
    __shared__ float lg[SS];
    __shared__ float red[256];
    __shared__ float ored[4][DKK];
    __shared__ __align__(16) float qs[DKK];

    const int gi = blockIdx.x >> 4;     // 0 or 1
    const int h  = blockIdx.x & 15;
    const int srow = gi ? (SS - 1) : 0;
    const int tid = threadIdx.x;

    if (tid < DKK) qs[tid] = g_q[(size_t)srow * DM + h * DKK + tid];
    __syncthreads();

    float lmax = -1e30f;
    for (int n = tid; n < SS; n += 256) {
        const float4* kr = (const float4*)(g_k + (size_t)n * DM + h * DKK);
        const float4* qr = (const float4*)qs;
        float dot = 0.0f;
#pragma unroll
        for (int i = 0; i < 16; i++) {
            float4 kv = kr[i], qv = qr[i];
            dot = fmaf(kv.x, qv.x, dot);
            dot = fmaf(kv.y, qv.y, dot);
            dot = fmaf(kv.z, qv.z, dot);
            dot = fmaf(kv.w, qv.w, dot);
        }
        float l = dot * SCALE;
        lg[n] = l;
        lmax = fmaxf(lmax, l);
    }
    red[tid] = lmax; __syncthreads();
    for (int st = 128; st; st >>= 1) {
        if (tid < st) red[tid] = fmaxf(red[tid], red[tid + st]);
        __syncthreads();
    }
    float m = red[0];
    __syncthreads();

    float lsum = 0.0f;
    for (int n = tid; n < SS; n += 256) {
        float e = __expf(lg[n] - m);
        lg[n] = e;
        lsum += e;
    }
    red[tid] = lsum; __syncthreads();
    for (int st = 128; st; st >>= 1) {
        if (tid < st) red[tid] += red[tid + st];
        __syncthreads();
    }
    float inv = 1.0f / red[0];
    __syncthreads();

    const int d = tid & 63;
    const int c = tid >> 6;
    float acc = 0.0f;
    const float* vb = g_v + h * DKK + d;
    const int n0 = c * (SS / 4), n1 = n0 + (SS / 4);
    for (int n = n0; n < n1; n++)
        acc = fmaf(lg[n], vb[(size_t)n * DM], acc);
    ored[c][d] = acc;
    __syncthreads();

    if (tid < DKK) {
        g_o[(size_t)srow * DM + h * DKK + tid] =
            (ored[0][tid] + ored[1][tid] + ored[2][tid] + ored[3][tid]) * inv;
    }
}

// ---------------------------------------------------------------------------
extern "C" void kernel_launch(void* const* d_in, const int* in_sizes, int n_in,
                              void* d_out, int out_size) {
    const float* Q  = (const float*)d_in[0];
    const float* Kk = (const float*)d_in[1];
    const float* V  = (const float*)d_in[2];
    const float* Wq = (const float*)d_in[3];
    const float* Wk = (const float*)d_in[4];
    const float* Wv = (const float*)d_in[5];
    const float* Wo = (const float*)d_in[6];
    const void*  idx = (const void*)d_in[7];
    float* out = (float*)d_out;

    float *pq, *pk, *pv, *po;
    cudaGetSymbolAddress((void**)&pq, g_q);
    cudaGetSymbolAddress((void**)&pk, g_k);
    cudaGetSymbolAddress((void**)&pv, g_v);
    cudaGetSymbolAddress((void**)&po, g_o);

    decode_idx<<<(NNG * KSEL + 255) / 256, 256>>>(idx);

    // fused QKV projections: grid.z selects (A, B, C) triple
    dim3 qkv_grid(DM / 128, SS / 128, 3);
    sgemm_tf32<<<qkv_grid, 256>>>(Q, Kk, V, Wq, Wk, Wv, pq, pk, pv);

    sparse_attn<<<(NNG * HH) / 4, 128>>>();
    global_attn<<<2 * HH, 256>>>();

    dim3 o_grid(DM / 128, SS / 128, 1);
    sgemm_tf32<<<o_grid, 256>>>(po, po, po, Wo, Wo, Wo, out, out, out);
}

// round 7
// speedup vs baseline: 1.6531x; 1.3169x over previous
#include <cuda_runtime.h>
#include <math.h>

#define SS   4096
#define DM   1024
#define HH   16
#define DKK  64
#define GG   1
#define NNG  (SS - 2*GG)     // 4094
#define KSEL 32
#define SCALE 0.125f         // 1/sqrt(64)

// Scratch (device globals — no allocation allowed)
__device__ float g_q[SS*DM];
__device__ float g_k[SS*DM];
__device__ float g_v[SS*DM];
__device__ float g_o[SS*DM];
__device__ int   g_sel[NNG*KSEL];
__device__ float g_gpart[2*HH*8*72];   // global-attn partials: [gi][h][split][72]

// ---------------------------------------------------------------------------
// Decode idx buffer (int64 or int32, sniffed from element layout).
// ---------------------------------------------------------------------------
__global__ void decode_idx(const void* __restrict__ raw) {
    int i = blockIdx.x * blockDim.x + threadIdx.x;
    if (i >= NNG * KSEL) return;
    const int* p32 = (const int*)raw;
    int v;
    if (p32[1] == 0) {
        v = (int)((const long long*)raw)[i];
    } else {
        v = p32[i];
    }
    g_sel[i] = v;
}

// ---------------------------------------------------------------------------
// TF32 tensor-core GEMM, k-permuted XOR-swizzled smem layout (unchanged).
// ---------------------------------------------------------------------------
#define BM 128
#define BN 128
#define BK 16

__device__ __forceinline__ float to_tf32(float x) {
    unsigned r;
    asm("cvt.rna.tf32.f32 %0, %1;" : "=r"(r) : "f"(x));
    return __uint_as_float(r);
}
__device__ __forceinline__ int swz(int x) { return (x ^ (x >> 2)) & 3; }

__device__ __forceinline__ void mma_tf32(float& c0, float& c1, float& c2, float& c3,
                                         float a0, float a1, float a2, float a3,
                                         float b0, float b1) {
    asm volatile(
        "mma.sync.aligned.m16n8k8.row.col.f32.tf32.tf32.f32 "
        "{%0,%1,%2,%3}, {%4,%5,%6,%7}, {%8,%9}, {%0,%1,%2,%3};"
        : "+f"(c0), "+f"(c1), "+f"(c2), "+f"(c3)
        : "r"(__float_as_uint(a0)), "r"(__float_as_uint(a1)),
          "r"(__float_as_uint(a2)), "r"(__float_as_uint(a3)),
          "r"(__float_as_uint(b0)), "r"(__float_as_uint(b1)));
}

__global__ __launch_bounds__(256, 2)
void sgemm_tf32(const float* __restrict__ A0, const float* __restrict__ A1,
                const float* __restrict__ A2, const float* __restrict__ B0,
                const float* __restrict__ B1, const float* __restrict__ B2,
                float* __restrict__ C0, float* __restrict__ C1,
                float* __restrict__ C2) {
    __shared__ float As[2][BM][16];
    __shared__ float Bs[2][BN][16];

    const int K = DM, N = DM;
    const float* A = (blockIdx.z == 0) ? A0 : (blockIdx.z == 1) ? A1 : A2;
    const float* B = (blockIdx.z == 0) ? B0 : (blockIdx.z == 1) ? B1 : B2;
    float*       C = (blockIdx.z == 0) ? C0 : (blockIdx.z == 1) ? C1 : C2;

    const int tid  = threadIdx.x;
    const int lane = tid & 31;
    const int warp = tid >> 5;
    const int wm   = warp & 3;
    const int wn   = warp >> 2;
    const int gid  = lane >> 2;
    const int qid  = lane & 3;
    const int t3   = tid & 3;

    const int bx = blockIdx.x;
    const int by = blockIdx.y;

    const float* Ab = A + (size_t)by * BM * K;
    const float* Bb = B + (size_t)bx * BN;

    const int ar0 = tid >> 2;
    const int ar1 = ar0 + 64;
    const int ac  = t3 * 4;
    const int br0 = tid >> 5;
    const int br1 = br0 + 8;
    const int bc  = (tid & 31) * 4;

    const int sa0 = swz(ar0), sa1 = swz(ar1);

    int arow[4], aoff[4];
#pragma unroll
    for (int i = 0; i < 4; i++) {
        arow[i] = wm * 32 + i * 8 + gid;
        aoff[i] = arow[i] * 16 + ((qid ^ swz(arow[i])) << 2);
    }
    int boff[8];
#pragma unroll
    for (int ni = 0; ni < 8; ni++) {
        int n = wn * 64 + ni * 8 + gid;
        boff[ni] = n * 16 + ((qid ^ swz(n)) << 2);
    }

    float acc[2][8][4];
#pragma unroll
    for (int mi = 0; mi < 2; mi++)
#pragma unroll
        for (int ni = 0; ni < 8; ni++)
#pragma unroll
            for (int r = 0; r < 4; r++) acc[mi][ni][r] = 0.0f;

    {
        float4 a0 = *(const float4*)(Ab + (size_t)ar0 * K + ac);
        float4 a1 = *(const float4*)(Ab + (size_t)ar1 * K + ac);
        float4 b0 = *(const float4*)(Bb + (size_t)br0 * N + bc);
        float4 b1 = *(const float4*)(Bb + (size_t)br1 * N + bc);
        float av0[4] = {a0.x, a0.y, a0.z, a0.w};
        float av1[4] = {a1.x, a1.y, a1.z, a1.w};
        float bv0[4] = {b0.x, b0.y, b0.z, b0.w};
        float bv1[4] = {b1.x, b1.y, b1.z, b1.w};
#pragma unroll
        for (int j = 0; j < 4; j++) {
            As[0][ar0][((j ^ sa0) << 2) + t3] = to_tf32(av0[j]);
            As[0][ar1][((j ^ sa1) << 2) + t3] = to_tf32(av1[j]);
            Bs[0][bc + j][(((br0 & 3) ^ j ^ t3) << 2) + (br0 >> 2)] = to_tf32(bv0[j]);
            Bs[0][bc + j][(((br1 & 3) ^ j ^ t3) << 2) + (br1 >> 2)] = to_tf32(bv1[j]);
        }
    }
    __syncthreads();

    const int nk = K / BK;
    float4 pa0, pa1, pb0, pb1;

    for (int kt = 0; kt < nk; kt++) {
        const int cur = kt & 1;

        if (kt + 1 < nk) {
            const int ko = (kt + 1) * BK;
            pa0 = *(const float4*)(Ab + (size_t)ar0 * K + ko + ac);
            pa1 = *(const float4*)(Ab + (size_t)ar1 * K + ko + ac);
            pb0 = *(const float4*)(Bb + (size_t)(ko + br0) * N + bc);
            pb1 = *(const float4*)(Bb + (size_t)(ko + br1) * N + bc);
        }

        float4 av[4];
        {
            const float* base = &As[cur][0][0];
#pragma unroll
            for (int i = 0; i < 4; i++)
                av[i] = *(const float4*)(base + aoff[i]);
        }

#pragma unroll
        for (int kc = 0; kc < 2; kc++) {
            float2 bv[8];
            {
                const float* base = &Bs[cur][0][0] + kc * 2;
#pragma unroll
                for (int ni = 0; ni < 8; ni++)
                    bv[ni] = *(const float2*)(base + boff[ni]);
            }
#pragma unroll
            for (int mi = 0; mi < 2; mi++) {
                const float4 lo = av[mi * 2];
                const float4 hi = av[mi * 2 + 1];
                const float a0 = kc ? lo.z : lo.x;
                const float a1 = kc ? hi.z : hi.x;
                const float a2 = kc ? lo.w : lo.y;
                const float a3 = kc ? hi.w : hi.y;
#pragma unroll
                for (int ni = 0; ni < 8; ni++)
                    mma_tf32(acc[mi][ni][0], acc[mi][ni][1], acc[mi][ni][2], acc[mi][ni][3],
                             a0, a1, a2, a3, bv[ni].x, bv[ni].y);
            }
        }

        if (kt + 1 < nk) {
            const int nxt = (kt + 1) & 1;
            float av0[4] = {pa0.x, pa0.y, pa0.z, pa0.w};
            float av1[4] = {pa1.x, pa1.y, pa1.z, pa1.w};
            float bv0[4] = {pb0.x, pb0.y, pb0.z, pb0.w};
            float bv1[4] = {pb1.x, pb1.y, pb1.z, pb1.w};
#pragma unroll
            for (int j = 0; j < 4; j++) {
                As[nxt][ar0][((j ^ sa0) << 2) + t3] = to_tf32(av0[j]);
                As[nxt][ar1][((j ^ sa1) << 2) + t3] = to_tf32(av1[j]);
                Bs[nxt][bc + j][(((br0 & 3) ^ j ^ t3) << 2) + (br0 >> 2)] = to_tf32(bv0[j]);
                Bs[nxt][bc + j][(((br1 & 3) ^ j ^ t3) << 2) + (br1 >> 2)] = to_tf32(bv1[j]);
            }
        }
        __syncthreads();
    }

#pragma unroll
    for (int mi = 0; mi < 2; mi++) {
        const int row = by * BM + wm * 32 + mi * 16 + gid;
#pragma unroll
        for (int ni = 0; ni < 8; ni++) {
            const int col = bx * BN + wn * 64 + ni * 8 + 2 * qid;
            *(float2*)(C + (size_t)row * N + col) =
                make_float2(acc[mi][ni][0], acc[mi][ni][1]);
            *(float2*)(C + (size_t)(row + 8) * N + col) =
                make_float2(acc[mi][ni][2], acc[mi][ni][3]);
        }
    }
}

// ---------------------------------------------------------------------------
// Sparse attention v3: CTA = 64 consecutive tokens x 1 head.
// Caches K/V rows [rowbase, rowbase+96) plus row 0 (slot 96) in smem;
// idx hits read smem, misses (random keys) fall back to L2. Correct for
// arbitrary idx — the cache is an optimization, not an assumption.
// ---------------------------------------------------------------------------
#define TB      64
#define CROWS   96
#define CSLOTS  97
#define CSTRIDE 68

__global__ __launch_bounds__(256)
void sparse_attn() {
    __shared__ float Kc[CSLOTS * CSTRIDE];
    __shared__ float Vc[CSLOTS * CSTRIDE];
    __shared__ float qsm[8][CSTRIDE];

    const int b    = blockIdx.x;      // token block
    const int h    = blockIdx.y;      // head
    const int tid  = threadIdx.x;
    const int lane = tid & 31;
    const int w    = tid >> 5;

    int rowbase = b * TB - 10;
    if (rowbase < 0) rowbase = 0;
    if (rowbase > SS - CROWS) rowbase = SS - CROWS;

    // cooperative cache fill: 97 rows x 16 float4 (K and V)
    for (int i = tid; i < CSLOTS * 16; i += 256) {
        const int r  = i >> 4;
        const int c4 = (i & 15) * 4;
        const int src = (r < CROWS) ? (rowbase + r) : 0;
        const float4 kv = *(const float4*)(g_k + (size_t)src * DM + h * DKK + c4);
        const float4 vv = *(const float4*)(g_v + (size_t)src * DM + h * DKK + c4);
        *(float4*)(Kc + r * CSTRIDE + c4) = kv;
        *(float4*)(Vc + r * CSTRIDE + c4) = vv;
    }
    __syncthreads();

    for (int i = 0; i < 8; i++) {
        const int t = b * TB + w * 8 + i;
        if (t >= NNG) break;

        // stage q row for this (token, head): 32 lanes x float2
        __syncwarp();
        *(float2*)(&qsm[w][2 * lane]) =
            *(const float2*)(g_q + (size_t)(t + GG) * DM + h * DKK + 2 * lane);
        __syncwarp();

        const int kidx = g_sel[t * KSEL + lane];
        int slot = kidx - rowbase;
        if (kidx == 0) slot = CROWS;                       // row 0 cached at slot 96
        else if (slot < 0 || slot >= CROWS) slot = -1;     // miss

        float dot = 0.0f;
        if (slot >= 0) {
            const float* kr = Kc + slot * CSTRIDE;
            const int rot = slot & 31;
#pragma unroll
            for (int pp = 0; pp < 32; pp++) {
                const int p = (pp + rot) & 31;
                const float2 kv = *(const float2*)(kr + 2 * p);
                const float2 qv = *(const float2*)(&qsm[w][2 * p]);
                dot += kv.x * qv.x + kv.y * qv.y;
            }
        } else {
            const float* kr = g_k + (size_t)kidx * DM + h * DKK;
            const int rot = lane;
#pragma unroll
            for (int pp = 0; pp < 32; pp++) {
                const int p = (pp + rot) & 31;
                const float2 kv = *(const float2*)(kr + 2 * p);
                const float2 qv = *(const float2*)(&qsm[w][2 * p]);
                dot += kv.x * qv.x + kv.y * qv.y;
            }
        }
        const float lg = dot * SCALE;

        float m = lg;
#pragma unroll
        for (int o = 16; o; o >>= 1) m = fmaxf(m, __shfl_xor_sync(0xffffffffu, m, o));
        const float e = __expf(lg - m);
        float sum = e;
#pragma unroll
        for (int o = 16; o; o >>= 1) sum += __shfl_xor_sync(0xffffffffu, sum, o);
        const float prob = e / sum;

        float acc0 = 0.0f, acc1 = 0.0f;
#pragma unroll
        for (int j = 0; j < 32; j++) {
            const float pj = __shfl_sync(0xffffffffu, prob, j);
            const int   sj = __shfl_sync(0xffffffffu, slot, j);
            const int   kj = __shfl_sync(0xffffffffu, kidx, j);
            if (sj >= 0) {
                acc0 = fmaf(pj, Vc[sj * CSTRIDE + lane],      acc0);
                acc1 = fmaf(pj, Vc[sj * CSTRIDE + lane + 32], acc1);
            } else {
                const float* vr = g_v + (size_t)kj * DM + h * DKK;
                acc0 = fmaf(pj, vr[lane],      acc0);
                acc1 = fmaf(pj, vr[lane + 32], acc1);
            }
        }
        float* orow = g_o + (size_t)(t + GG) * DM + h * DKK;
        orow[lane]      = acc0;
        orow[lane + 32] = acc1;
    }
}

// ---------------------------------------------------------------------------
// Global attention, split-K: grid (8 splits, 16 heads, 2 tokens).
// Each block: 512 keys -> partial (m, sum, acc[64]) into g_gpart.
// ---------------------------------------------------------------------------
__global__ __launch_bounds__(256)
void global_attn_split() {
    __shared__ float lg[512];
    __shared__ float red[256];
    __shared__ float ored[4][DKK];
    __shared__ __align__(16) float qs[DKK];

    const int spl = blockIdx.x;     // 0..7
    const int h   = blockIdx.y;     // 0..15
    const int gi  = blockIdx.z;     // 0..1
    const int srow = gi ? (SS - 1) : 0;
    const int tid = threadIdx.x;
    const int n0  = spl * 512;

    if (tid < DKK) qs[tid] = g_q[(size_t)srow * DM + h * DKK + tid];
    __syncthreads();

    float lmax = -1e30f;
#pragma unroll
    for (int u = 0; u < 2; u++) {
        const int nl = u * 256 + tid;
        const int n  = n0 + nl;
        const float4* kr = (const float4*)(g_k + (size_t)n * DM + h * DKK);
        const float4* qr = (const float4*)qs;
        float dot = 0.0f;
#pragma unroll
        for (int i = 0; i < 16; i++) {
            float4 kv = kr[i], qv = qr[i];
            dot = fmaf(kv.x, qv.x, dot);
            dot = fmaf(kv.y, qv.y, dot);
            dot = fmaf(kv.z, qv.z, dot);
            dot = fmaf(kv.w, qv.w, dot);
        }
        const float l = dot * SCALE;
        lg[nl] = l;
        lmax = fmaxf(lmax, l);
    }
    red[tid] = lmax; __syncthreads();
    for (int st = 128; st; st >>= 1) {
        if (tid < st) red[tid] = fmaxf(red[tid], red[tid + st]);
        __syncthreads();
    }
    const float m = red[0];
    __syncthreads();

    float lsum = 0.0f;
#pragma unroll
    for (int u = 0; u < 2; u++) {
        const int nl = u * 256 + tid;
        const float e = __expf(lg[nl] - m);
        lg[nl] = e;
        lsum += e;
    }
    red[tid] = lsum; __syncthreads();
    for (int st = 128; st; st >>= 1) {
        if (tid < st) red[tid] += red[tid + st];
        __syncthreads();
    }
    const float s = red[0];
    __syncthreads();

    // PV: thread (c, d) accumulates quarter c of this split's 512 keys
    const int d = tid & 63;
    const int c = tid >> 6;
    float acc = 0.0f;
    const float* vb = g_v + h * DKK + d;
    const int na = c * 128, nb = na + 128;
    for (int nl = na; nl < nb; nl++)
        acc = fmaf(lg[nl], vb[(size_t)(n0 + nl) * DM], acc);
    ored[c][d] = acc;
    __syncthreads();

    const int base = ((gi * HH + h) * 8 + spl) * 72;
    if (tid < DKK)
        g_gpart[base + tid] = ored[0][tid] + ored[1][tid] + ored[2][tid] + ored[3][tid];
    else if (tid == 64) g_gpart[base + 64] = m;
    else if (tid == 65) g_gpart[base + 65] = s;
}

__global__ __launch_bounds__(64)
void global_attn_combine() {
    const int blk = blockIdx.x;     // gi*16 + h
    const int d   = threadIdx.x;    // 0..63
    const int gi  = blk >> 4;
    const int h   = blk & 15;
    const int srow = gi ? (SS - 1) : 0;

    float M = -1e30f;
#pragma unroll
    for (int i = 0; i < 8; i++)
        M = fmaxf(M, g_gpart[(blk * 8 + i) * 72 + 64]);
    float S = 0.0f, acc = 0.0f;
#pragma unroll
    for (int i = 0; i < 8; i++) {
        const int base = (blk * 8 + i) * 72;
        const float wgt = __expf(g_gpart[base + 64] - M);
        S   += g_gpart[base + 65] * wgt;
        acc += g_gpart[base + d] * wgt;
    }
    g_o[(size_t)srow * DM + h * DKK + d] = acc / S;
}

// ---------------------------------------------------------------------------
extern "C" void kernel_launch(void* const* d_in, const int* in_sizes, int n_in,
                              void* d_out, int out_size) {
    const float* Q  = (const float*)d_in[0];
    const float* Kk = (const float*)d_in[1];
    const float* V  = (const float*)d_in[2];
    const float* Wq = (const float*)d_in[3];
    const float* Wk = (const float*)d_in[4];
    const float* Wv = (const float*)d_in[5];
    const float* Wo = (const float*)d_in[6];
    const void*  idx = (const void*)d_in[7];
    float* out = (float*)d_out;

    float *pq, *pk, *pv, *po;
    cudaGetSymbolAddress((void**)&pq, g_q);
    cudaGetSymbolAddress((void**)&pk, g_k);
    cudaGetSymbolAddress((void**)&pv, g_v);
    cudaGetSymbolAddress((void**)&po, g_o);

    decode_idx<<<(NNG * KSEL + 255) / 256, 256>>>(idx);

    dim3 qkv_grid(DM / 128, SS / 128, 3);
    sgemm_tf32<<<qkv_grid, 256>>>(Q, Kk, V, Wq, Wk, Wv, pq, pk, pv);

    dim3 sp_grid((NNG + TB - 1) / TB, HH);   // (64, 16)
    sparse_attn<<<sp_grid, 256>>>();

    dim3 gs_grid(8, HH, 2);
    global_attn_split<<<gs_grid, 256>>>();
    global_attn_combine<<<2 * HH, 64>>>();

    dim3 o_grid(DM / 128, SS / 128, 1);
    sgemm_tf32<<<o_grid, 256>>>(po, po, po, Wo, Wo, Wo, out, out, out);
}

// round 11
// speedup vs baseline: 2.1735x; 1.3148x over previous
#include <cuda_runtime.h>
#include <math.h>
#include <stdint.h>

#define SS   4096
#define DM   1024
#define HH   16
#define DKK  64
#define GG   1
#define NNG  (SS - 2*GG)     // 4094
#define KSEL 32
#define SCALE 0.125f         // 1/sqrt(64)

// Scratch (device globals — no allocation allowed)
__device__ float g_q[SS*DM];
__device__ float g_k[SS*DM];
__device__ float g_v[SS*DM];
__device__ float g_o[SS*DM];
__device__ int   g_sel[NNG*KSEL];
__device__ float g_gpart[2*HH*8*72];   // global-attn partials

// ---------------------------------------------------------------------------
// Decode idx buffer (int64 or int32, sniffed from element layout).
// ---------------------------------------------------------------------------
__global__ void decode_idx(const void* __restrict__ raw) {
    int i = blockIdx.x * blockDim.x + threadIdx.x;
    if (i >= NNG * KSEL) return;
    const int* p32 = (const int*)raw;
    int v;
    if (p32[1] == 0) {
        v = (int)((const long long*)raw)[i];
    } else {
        v = p32[i];
    }
    g_sel[i] = v;
}

// ===========================================================================
// TF32 mma.sync GEMM v2: CTA tile 128x256, BK=16, 8 warps (2M x 4N),
// warp tile 64x64 (4x8 m16n8k8 mmas per k-chunk of 8).
// k-permuted XOR-swizzled smem: element (k, x) of a tile lives at
//   x*16 + ((k&3) ^ swz4(x))*4 + (k>>2)        (floats)
// so one LDS.128 per (row, qid) delivers k = qid + {0,4,8,12}.
// grid.z selects one of up to 3 (A, B, C) triples (fused QKV).
// ===========================================================================
#define BM2 128
#define BN2 256
#define GS_A 0                     // As: 2 bufs x 128 x 16 floats
#define GS_B 4096                  // Bs: 2 bufs x 256 x 16 floats
#define GSMEM2 49152               // 48 KB

__device__ __forceinline__ float to_tf32(float x) {
    unsigned r;
    asm("cvt.rna.tf32.f32 %0, %1;" : "=r"(r) : "f"(x));
    return __uint_as_float(r);
}
__device__ __forceinline__ int swz4(int x) { return (x ^ (x >> 2) ^ (x >> 4)) & 3; }

__device__ __forceinline__ void mma_tf32(float& c0, float& c1, float& c2, float& c3,
                                         float a0, float a1, float a2, float a3,
                                         float b0, float b1) {
    asm volatile(
        "mma.sync.aligned.m16n8k8.row.col.f32.tf32.tf32.f32 "
        "{%0,%1,%2,%3}, {%4,%5,%6,%7}, {%8,%9}, {%0,%1,%2,%3};"
        : "+f"(c0), "+f"(c1), "+f"(c2), "+f"(c3)
        : "r"(__float_as_uint(a0)), "r"(__float_as_uint(a1)),
          "r"(__float_as_uint(a2)), "r"(__float_as_uint(a3)),
          "r"(__float_as_uint(b0)), "r"(__float_as_uint(b1)));
}

__global__ __launch_bounds__(256, 1)
void gemm_mma2(const float* __restrict__ A0, const float* __restrict__ A1,
               const float* __restrict__ A2, const float* __restrict__ B0,
               const float* __restrict__ B1, const float* __restrict__ B2,
               float* __restrict__ C0, float* __restrict__ C1,
               float* __restrict__ C2) {
    extern __shared__ float dsm[];

    const int K = DM, N = DM;
    const float* A = (blockIdx.z == 0) ? A0 : (blockIdx.z == 1) ? A1 : A2;
    const float* B = (blockIdx.z == 0) ? B0 : (blockIdx.z == 1) ? B1 : B2;
    float*       C = (blockIdx.z == 0) ? C0 : (blockIdx.z == 1) ? C1 : C2;

    const int tid  = threadIdx.x;
    const int lane = tid & 31;
    const int warp = tid >> 5;
    const int wm   = warp >> 2;       // 0..1 -> M (64 rows each)
    const int wn   = warp & 3;        // 0..3 -> N (64 cols each)
    const int gid  = lane >> 2;       // 0..7
    const int qid  = lane & 3;        // 0..3

    const int bx = blockIdx.x;        // N tile (256)
    const int by = blockIdx.y;        // M tile (128)

    // --- fill mappings ---
    // A: thread -> row am (0..127), k-half ah in {0,8}; 2x LDG.128 + 8 STS.32
    const int am = tid >> 1;
    const int ah = (tid & 1) * 8;
    const float* Abase = A + (size_t)(by * BM2 + am) * K + ah;
    const int sa = swz4(am);
    // B: thread -> col bn (0..255), all 16 k; 16x LDG.32 + 16 STS.32
    const int bn = tid;
    const float* Bbase = B + bx * BN2 + bn;
    const int sbz = swz4(bn);

    // --- fragment smem offsets (floats within one buffer) ---
    int aoff[8];   // 4 m-subtiles x rows (gid, gid+8)
#pragma unroll
    for (int mi = 0; mi < 4; mi++) {
#pragma unroll
        for (int r = 0; r < 2; r++) {
            const int row = wm * 64 + mi * 16 + r * 8 + gid;
            aoff[mi * 2 + r] = row * 16 + ((qid ^ swz4(row)) << 2);
        }
    }
    int boff[8];
#pragma unroll
    for (int ni = 0; ni < 8; ni++) {
        const int col = wn * 64 + ni * 8 + gid;
        boff[ni] = col * 16 + ((qid ^ swz4(col)) << 2);
    }

    float acc[4][8][4];
#pragma unroll
    for (int mi = 0; mi < 4; mi++)
#pragma unroll
        for (int ni = 0; ni < 8; ni++)
#pragma unroll
            for (int r = 0; r < 4; r++) acc[mi][ni][r] = 0.0f;

    // --- load tile 0 into buffer 0 ---
    {
        float4 a0 = *(const float4*)(Abase);
        float4 a1 = *(const float4*)(Abase + 4);
        float bv[16];
#pragma unroll
        for (int j = 0; j < 16; j++) bv[j] = Bbase[(size_t)j * N];

        float av0[4] = {a0.x, a0.y, a0.z, a0.w};
        float av1[4] = {a1.x, a1.y, a1.z, a1.w};
        const int s0 = (ah >> 2), s1 = s0 + 1;     // slots: k>>2
#pragma unroll
        for (int e = 0; e < 4; e++) {
            dsm[GS_A + am * 16 + ((e ^ sa) << 2) + s0] = to_tf32(av0[e]);
            dsm[GS_A + am * 16 + ((e ^ sa) << 2) + s1] = to_tf32(av1[e]);
        }
#pragma unroll
        for (int j = 0; j < 16; j++)
            dsm[GS_B + bn * 16 + (((j & 3) ^ sbz) << 2) + (j >> 2)] = to_tf32(bv[j]);
    }
    __syncthreads();

    const int nk = K / 16;    // 64
    float4 pa0, pa1;
    float pb[16];

    for (int kt = 0; kt < nk; kt++) {
        const int cur = kt & 1;
        const float* abuf = dsm + GS_A + cur * 2048;
        const float* bbuf = dsm + GS_B + cur * 4096;

        // prefetch next tile into registers
        if (kt + 1 < nk) {
            const int ko = (kt + 1) * 16;
            pa0 = *(const float4*)(Abase + ko);
            pa1 = *(const float4*)(Abase + ko + 4);
#pragma unroll
            for (int j = 0; j < 16; j++)
                pb[j] = Bbase[(size_t)(ko + j) * N];
        }

        // fragment loads: one LDS.128 each covers k = qid + {0,4,8,12}
        float4 av[8], bv[8];
#pragma unroll
        for (int i = 0; i < 8; i++) av[i] = *(const float4*)(abuf + aoff[i]);
#pragma unroll
        for (int i = 0; i < 8; i++) bv[i] = *(const float4*)(bbuf + boff[i]);

        // kc = 0 uses (.x, .y); kc = 1 uses (.z, .w)
#pragma unroll
        for (int kc = 0; kc < 2; kc++) {
#pragma unroll
            for (int mi = 0; mi < 4; mi++) {
                const float4 lo = av[mi * 2];
                const float4 hi = av[mi * 2 + 1];
                const float a0 = kc ? lo.z : lo.x;
                const float a1 = kc ? hi.z : hi.x;
                const float a2 = kc ? lo.w : lo.y;
                const float a3 = kc ? hi.w : hi.y;
#pragma unroll
                for (int ni = 0; ni < 8; ni++) {
                    const float b0 = kc ? bv[ni].z : bv[ni].x;
                    const float b1 = kc ? bv[ni].w : bv[ni].y;
                    mma_tf32(acc[mi][ni][0], acc[mi][ni][1],
                             acc[mi][ni][2], acc[mi][ni][3],
                             a0, a1, a2, a3, b0, b1);
                }
            }
        }

        // store prefetched tile into the other buffer
        if (kt + 1 < nk) {
            const int nxt = (kt + 1) & 1;
            float* anb = dsm + GS_A + nxt * 2048;
            float* bnb = dsm + GS_B + nxt * 4096;
            float av0[4] = {pa0.x, pa0.y, pa0.z, pa0.w};
            float av1[4] = {pa1.x, pa1.y, pa1.z, pa1.w};
            const int s0 = (ah >> 2), s1 = s0 + 1;
#pragma unroll
            for (int e = 0; e < 4; e++) {
                anb[am * 16 + ((e ^ sa) << 2) + s0] = to_tf32(av0[e]);
                anb[am * 16 + ((e ^ sa) << 2) + s1] = to_tf32(av1[e]);
            }
#pragma unroll
            for (int j = 0; j < 16; j++)
                bnb[bn * 16 + (((j & 3) ^ sbz) << 2) + (j >> 2)] = to_tf32(pb[j]);
        }
        __syncthreads();
    }

    // epilogue
#pragma unroll
    for (int mi = 0; mi < 4; mi++) {
        const int row = by * BM2 + wm * 64 + mi * 16 + gid;
#pragma unroll
        for (int ni = 0; ni < 8; ni++) {
            const int col = bx * BN2 + wn * 64 + ni * 8 + 2 * qid;
            *(float2*)(C + (size_t)row * N + col) =
                make_float2(acc[mi][ni][0], acc[mi][ni][1]);
            *(float2*)(C + (size_t)(row + 8) * N + col) =
                make_float2(acc[mi][ni][2], acc[mi][ni][3]);
        }
    }
}

// ---------------------------------------------------------------------------
// Sparse attention v3 (unchanged): CTA = 64 tokens x 1 head, smem K/V cache.
// ---------------------------------------------------------------------------
#define TB      64
#define CROWS   96
#define CSLOTS  97
#define CSTRIDE 68

__global__ __launch_bounds__(256)
void sparse_attn() {
    __shared__ float Kc[CSLOTS * CSTRIDE];
    __shared__ float Vc[CSLOTS * CSTRIDE];
    __shared__ float qsm[8][CSTRIDE];

    const int b    = blockIdx.x;
    const int h    = blockIdx.y;
    const int tid  = threadIdx.x;
    const int lane = tid & 31;
    const int w    = tid >> 5;

    int rowbase = b * TB - 10;
    if (rowbase < 0) rowbase = 0;
    if (rowbase > SS - CROWS) rowbase = SS - CROWS;

    for (int i = tid; i < CSLOTS * 16; i += 256) {
        const int r  = i >> 4;
        const int c4 = (i & 15) * 4;
        const int src = (r < CROWS) ? (rowbase + r) : 0;
        const float4 kv = *(const float4*)(g_k + (size_t)src * DM + h * DKK + c4);
        const float4 vv = *(const float4*)(g_v + (size_t)src * DM + h * DKK + c4);
        *(float4*)(Kc + r * CSTRIDE + c4) = kv;
        *(float4*)(Vc + r * CSTRIDE + c4) = vv;
    }
    __syncthreads();

    for (int i = 0; i < 8; i++) {
        const int t = b * TB + w * 8 + i;
        if (t >= NNG) break;

        __syncwarp();
        *(float2*)(&qsm[w][2 * lane]) =
            *(const float2*)(g_q + (size_t)(t + GG) * DM + h * DKK + 2 * lane);
        __syncwarp();

        const int kidx = g_sel[t * KSEL + lane];
        int slot = kidx - rowbase;
        if (kidx == 0) slot = CROWS;
        else if (slot < 0 || slot >= CROWS) slot = -1;

        float dot = 0.0f;
        if (slot >= 0) {
            const float* kr = Kc + slot * CSTRIDE;
            const int rot = slot & 31;
#pragma unroll
            for (int pp = 0; pp < 32; pp++) {
                const int p = (pp + rot) & 31;
                const float2 kv = *(const float2*)(kr + 2 * p);
                const float2 qv = *(const float2*)(&qsm[w][2 * p]);
                dot += kv.x * qv.x + kv.y * qv.y;
            }
        } else {
            const float* kr = g_k + (size_t)kidx * DM + h * DKK;
            const int rot = lane;
#pragma unroll
            for (int pp = 0; pp < 32; pp++) {
                const int p = (pp + rot) & 31;
                const float2 kv = *(const float2*)(kr + 2 * p);
                const float2 qv = *(const float2*)(&qsm[w][2 * p]);
                dot += kv.x * qv.x + kv.y * qv.y;
            }
        }
        const float lg = dot * SCALE;

        float m = lg;
#pragma unroll
        for (int o = 16; o; o >>= 1) m = fmaxf(m, __shfl_xor_sync(0xffffffffu, m, o));
        const float e = __expf(lg - m);
        float sum = e;
#pragma unroll
        for (int o = 16; o; o >>= 1) sum += __shfl_xor_sync(0xffffffffu, sum, o);
        const float prob = e / sum;

        float acc0 = 0.0f, acc1 = 0.0f;
#pragma unroll
        for (int j = 0; j < 32; j++) {
            const float pj = __shfl_sync(0xffffffffu, prob, j);
            const int   sj = __shfl_sync(0xffffffffu, slot, j);
            const int   kj = __shfl_sync(0xffffffffu, kidx, j);
            if (sj >= 0) {
                acc0 = fmaf(pj, Vc[sj * CSTRIDE + lane],      acc0);
                acc1 = fmaf(pj, Vc[sj * CSTRIDE + lane + 32], acc1);
            } else {
                const float* vr = g_v + (size_t)kj * DM + h * DKK;
                acc0 = fmaf(pj, vr[lane],      acc0);
                acc1 = fmaf(pj, vr[lane + 32], acc1);
            }
        }
        float* orow = g_o + (size_t)(t + GG) * DM + h * DKK;
        orow[lane]      = acc0;
        orow[lane + 32] = acc1;
    }
}

// ---------------------------------------------------------------------------
// Global attention split-K (unchanged).
// ---------------------------------------------------------------------------
__global__ __launch_bounds__(256)
void global_attn_split() {
    __shared__ float lg[512];
    __shared__ float red[256];
    __shared__ float ored[4][DKK];
    __shared__ __align__(16) float qs[DKK];

    const int spl = blockIdx.x;
    const int h   = blockIdx.y;
    const int gi  = blockIdx.z;
    const int srow = gi ? (SS - 1) : 0;
    const int tid = threadIdx.x;
    const int n0  = spl * 512;

    if (tid < DKK) qs[tid] = g_q[(size_t)srow * DM + h * DKK + tid];
    __syncthreads();

    float lmax = -1e30f;
#pragma unroll
    for (int u = 0; u < 2; u++) {
        const int nl = u * 256 + tid;
        const int n  = n0 + nl;
        const float4* kr = (const float4*)(g_k + (size_t)n * DM + h * DKK);
        const float4* qr = (const float4*)qs;
        float dot = 0.0f;
#pragma unroll
        for (int i = 0; i < 16; i++) {
            float4 kv = kr[i], qv = qr[i];
            dot = fmaf(kv.x, qv.x, dot);
            dot = fmaf(kv.y, qv.y, dot);
            dot = fmaf(kv.z, qv.z, dot);
            dot = fmaf(kv.w, qv.w, dot);
        }
        const float l = dot * SCALE;
        lg[nl] = l;
        lmax = fmaxf(lmax, l);
    }
    red[tid] = lmax; __syncthreads();
    for (int st = 128; st; st >>= 1) {
        if (tid < st) red[tid] = fmaxf(red[tid], red[tid + st]);
        __syncthreads();
    }
    const float m = red[0];
    __syncthreads();

    float lsum = 0.0f;
#pragma unroll
    for (int u = 0; u < 2; u++) {
        const int nl = u * 256 + tid;
        const float e = __expf(lg[nl] - m);
        lg[nl] = e;
        lsum += e;
    }
    red[tid] = lsum; __syncthreads();
    for (int st = 128; st; st >>= 1) {
        if (tid < st) red[tid] += red[tid + st];
        __syncthreads();
    }
    const float s = red[0];
    __syncthreads();

    const int d = tid & 63;
    const int c = tid >> 6;
    float acc = 0.0f;
    const float* vb = g_v + h * DKK + d;
    const int na = c * 128, nb = na + 128;
    for (int nl = na; nl < nb; nl++)
        acc = fmaf(lg[nl], vb[(size_t)(n0 + nl) * DM], acc);
    ored[c][d] = acc;
    __syncthreads();

    const int base = ((gi * HH + h) * 8 + spl) * 72;
    if (tid < DKK)
        g_gpart[base + tid] = ored[0][tid] + ored[1][tid] + ored[2][tid] + ored[3][tid];
    else if (tid == 64) g_gpart[base + 64] = m;
    else if (tid == 65) g_gpart[base + 65] = s;
}

__global__ __launch_bounds__(64)
void global_attn_combine() {
    const int blk = blockIdx.x;
    const int d   = threadIdx.x;
    const int gi  = blk >> 4;
    const int h   = blk & 15;
    const int srow = gi ? (SS - 1) : 0;

    float M = -1e30f;
#pragma unroll
    for (int i = 0; i < 8; i++)
        M = fmaxf(M, g_gpart[(blk * 8 + i) * 72 + 64]);
    float S = 0.0f, acc = 0.0f;
#pragma unroll
    for (int i = 0; i < 8; i++) {
        const int base = (blk * 8 + i) * 72;
        const float wgt = __expf(g_gpart[base + 64] - M);
        S   += g_gpart[base + 65] * wgt;
        acc += g_gpart[base + d] * wgt;
    }
    g_o[(size_t)srow * DM + h * DKK + d] = acc / S;
}

// ---------------------------------------------------------------------------
extern "C" void kernel_launch(void* const* d_in, const int* in_sizes, int n_in,
                              void* d_out, int out_size) {
    const float* Q  = (const float*)d_in[0];
    const float* Kk = (const float*)d_in[1];
    const float* V  = (const float*)d_in[2];
    const float* Wq = (const float*)d_in[3];
    const float* Wk = (const float*)d_in[4];
    const float* Wv = (const float*)d_in[5];
    const float* Wo = (const float*)d_in[6];
    const void*  idx = (const void*)d_in[7];
    float* out = (float*)d_out;

    float *pq, *pk, *pv, *po;
    cudaGetSymbolAddress((void**)&pq, g_q);
    cudaGetSymbolAddress((void**)&pk, g_k);
    cudaGetSymbolAddress((void**)&pv, g_v);
    cudaGetSymbolAddress((void**)&po, g_o);

    cudaFuncSetAttribute(gemm_mma2, cudaFuncAttributeMaxDynamicSharedMemorySize, GSMEM2);

    decode_idx<<<(NNG * KSEL + 255) / 256, 256>>>(idx);

    dim3 qkv_grid(DM / BN2, SS / BM2, 3);   // (4, 32, 3)
    gemm_mma2<<<qkv_grid, 256, GSMEM2>>>(Q, Kk, V, Wq, Wk, Wv, pq, pk, pv);

    dim3 sp_grid((NNG + TB - 1) / TB, HH);
    sparse_attn<<<sp_grid, 256>>>();

    dim3 gs_grid(8, HH, 2);
    global_attn_split<<<gs_grid, 256>>>();
    global_attn_combine<<<2 * HH, 64>>>();

    dim3 o_grid(DM / BN2, SS / BM2, 1);     // (4, 32, 1)
    gemm_mma2<<<o_grid, 256, GSMEM2>>>(po, po, po, Wo, Wo, Wo, out, out, out);
}

// round 12
// speedup vs baseline: 2.8946x; 1.3318x over previous
#include <cuda_runtime.h>
#include <cuda_fp16.h>
#include <math.h>
#include <stdint.h>

#define SS   4096
#define DM   1024
#define HH   16
#define DKK  64
#define GG   1
#define NNG  (SS - 2*GG)     // 4094
#define KSEL 32
#define SCALE 0.125f         // 1/sqrt(64)
#define NSPL 16

// Scratch (device globals — no allocation allowed)
__device__ float g_q[SS*DM];
__device__ float g_k[SS*DM];
__device__ float g_v[SS*DM];
__device__ float g_o[SS*DM];
__device__ float g_gpart[2*HH*NSPL*72];   // global-attn partials

// ===========================================================================
// FP16 mma.sync GEMM v3: CTA tile 128x256, BK=32 halves, 8 warps (2M x 4N),
// warp tile 64x64. Operands via ldmatrix; f32 accumulate.
//  A smem: [128 m-rows][32 k-halves], row stride 80B (padded; conflict-free
//          ldmatrix since bank-group = (5m + c) mod 8).
//  B smem: [32 k-rows][256 n-halves], row stride 512B, 16B-chunk XOR swizzle
//          p = (c & 24) | ((c&7) ^ (r&7)); read with ldmatrix.x4.trans.
// grid.z selects one of up to 3 (A, B, C) triples (fused QKV).
// ===========================================================================
#define BM3 128
#define BN3 256
#define A_STRIDE 80
#define A_BUF    10240      // 128*80
#define B_OFF    20480      // 2*A_BUF
#define B_BUF    16384      // 32*512
#define GSMEM3   53248      // 2*A_BUF + 2*B_BUF

__device__ __forceinline__ uint32_t smem_u32(const void* p) {
    uint32_t a;
    asm("{ .reg .u64 t; cvta.to.shared.u64 t, %1; cvt.u32.u64 %0, t; }"
        : "=r"(a) : "l"(p));
    return a;
}
__device__ __forceinline__ uint32_t fpack(float a, float b) {
    __half2 h = __floats2half2_rn(a, b);
    return *reinterpret_cast<uint32_t*>(&h);
}

#define LDM_X4(r, a) \
    asm volatile("ldmatrix.sync.aligned.m8n8.x4.shared.b16 {%0,%1,%2,%3}, [%4];" \
        : "=r"((r)[0]), "=r"((r)[1]), "=r"((r)[2]), "=r"((r)[3]) : "r"(a))
#define LDM_X4T(r, a) \
    asm volatile("ldmatrix.sync.aligned.m8n8.x4.trans.shared.b16 {%0,%1,%2,%3}, [%4];" \
        : "=r"((r)[0]), "=r"((r)[1]), "=r"((r)[2]), "=r"((r)[3]) : "r"(a))

__device__ __forceinline__ void mma_f16(float& c0, float& c1, float& c2, float& c3,
                                        uint32_t a0, uint32_t a1, uint32_t a2, uint32_t a3,
                                        uint32_t b0, uint32_t b1) {
    asm volatile(
        "mma.sync.aligned.m16n8k16.row.col.f32.f16.f16.f32 "
        "{%0,%1,%2,%3}, {%4,%5,%6,%7}, {%8,%9}, {%0,%1,%2,%3};"
        : "+f"(c0), "+f"(c1), "+f"(c2), "+f"(c3)
        : "r"(a0), "r"(a1), "r"(a2), "r"(a3), "r"(b0), "r"(b1));
}

__global__ __launch_bounds__(256, 1)
void gemm_f16(const float* __restrict__ A0, const float* __restrict__ A1,
              const float* __restrict__ A2, const float* __restrict__ B0,
              const float* __restrict__ B1, const float* __restrict__ B2,
              float* __restrict__ C0, float* __restrict__ C1,
              float* __restrict__ C2) {
    extern __shared__ char dsm[];
    const uint32_t sb = smem_u32(dsm);

    const int N = DM;
    const float* A = (blockIdx.z == 0) ? A0 : (blockIdx.z == 1) ? A1 : A2;
    const float* B = (blockIdx.z == 0) ? B0 : (blockIdx.z == 1) ? B1 : B2;
    float*       C = (blockIdx.z == 0) ? C0 : (blockIdx.z == 1) ? C1 : C2;

    const int tid  = threadIdx.x;
    const int lane = tid & 31;
    const int warp = tid >> 5;
    const int wm   = warp >> 2;       // 0..1
    const int wn   = warp & 3;        // 0..3
    const int gid  = lane >> 2;       // 0..7
    const int qid  = lane & 3;        // 0..3
    const int bx = blockIdx.x;        // N tile (256)
    const int by = blockIdx.y;        // M tile (128)

    // --- fill mappings ---
    // A: thread -> m = tid>>1 (0..127), cp = tid&1; 4 LDG.128, 2 STS.128
    const int am = tid >> 1;
    const int acp = tid & 1;
    const float* Ag = A + (size_t)(by * BM3 + am) * DM + acp * 16;
    const uint32_t aoffS = am * A_STRIDE + acp * 32;   // bytes
    // B: thread -> r = tid>>3 (0..31), cb = tid&7; 8 LDG.128, 4 STS.128
    const int br = tid >> 3;
    const int bcb = tid & 7;
    const float* Bg = B + (size_t)br * DM + bx * BN3 + bcb * 8;
    uint32_t boffS[4];
#pragma unroll
    for (int jj = 0; jj < 4; jj++)
        boffS[jj] = br * 512 + (8 * jj + (bcb ^ (br & 7))) * 16;

    // --- ldmatrix lane bases ---
    // A: matrices for (mi, kc) at aBase + mi*1280 + kc*32
    const uint32_t aBase0 = (uint32_t)((wm * 64 + (lane & 7) + ((lane >> 3) & 1) * 8) * A_STRIDE
                                       + (lane >> 4) * 16);
    // B: for ni: bBase + ((ni ^ (lane&7)) << 4)
    const uint32_t bBase0 = (uint32_t)(lane * 512 + wn * 128);
    const int lx = lane & 7;

    float acc[4][8][4];
#pragma unroll
    for (int mi = 0; mi < 4; mi++)
#pragma unroll
        for (int ni = 0; ni < 8; ni++)
#pragma unroll
            for (int r = 0; r < 4; r++) acc[mi][ni][r] = 0.0f;

    float4 pa[4], pb[8];

    // ---- prologue: stage 0 ----
#pragma unroll
    for (int j = 0; j < 4; j++) pa[j] = *(const float4*)(Ag + j * 4);
#pragma unroll
    for (int jj = 0; jj < 4; jj++) {
        pb[2 * jj]     = *(const float4*)(Bg + jj * 64);
        pb[2 * jj + 1] = *(const float4*)(Bg + jj * 64 + 4);
    }
    {
        char* ab = dsm + aoffS;
        *(uint4*)(ab)      = make_uint4(fpack(pa[0].x, pa[0].y), fpack(pa[0].z, pa[0].w),
                                        fpack(pa[1].x, pa[1].y), fpack(pa[1].z, pa[1].w));
        *(uint4*)(ab + 16) = make_uint4(fpack(pa[2].x, pa[2].y), fpack(pa[2].z, pa[2].w),
                                        fpack(pa[3].x, pa[3].y), fpack(pa[3].z, pa[3].w));
#pragma unroll
        for (int jj = 0; jj < 4; jj++) {
            *(uint4*)(dsm + B_OFF + boffS[jj]) =
                make_uint4(fpack(pb[2*jj].x, pb[2*jj].y), fpack(pb[2*jj].z, pb[2*jj].w),
                           fpack(pb[2*jj+1].x, pb[2*jj+1].y), fpack(pb[2*jj+1].z, pb[2*jj+1].w));
        }
    }
    __syncthreads();

    const int NITER = DM / 32;   // 32
    for (int it = 0; it < NITER; it++) {
        const int cur = it & 1;

        // prefetch next stage
        if (it + 1 < NITER) {
            const int k0 = (it + 1) * 32;
#pragma unroll
            for (int j = 0; j < 4; j++) pa[j] = *(const float4*)(Ag + k0 + j * 4);
            const float* Bg2 = Bg + (size_t)k0 * DM;
#pragma unroll
            for (int jj = 0; jj < 4; jj++) {
                pb[2 * jj]     = *(const float4*)(Bg2 + jj * 64);
                pb[2 * jj + 1] = *(const float4*)(Bg2 + jj * 64 + 4);
            }
        }

        // fragments
        const uint32_t aB = sb + cur * A_BUF + aBase0;
        const uint32_t bB = sb + B_OFF + cur * B_BUF + bBase0;
        uint32_t afr[8][4];    // [mi*2+kc]
#pragma unroll
        for (int mi = 0; mi < 4; mi++) {
            LDM_X4(afr[mi * 2 + 0], aB + mi * (16 * A_STRIDE) + 0);
            LDM_X4(afr[mi * 2 + 1], aB + mi * (16 * A_STRIDE) + 32);
        }
        uint32_t bfr[8][4];    // [ni]: r0,r1 = kc0; r2,r3 = kc1
#pragma unroll
        for (int ni = 0; ni < 8; ni++)
            LDM_X4T(bfr[ni], bB + ((ni ^ lx) << 4));

        // MMAs
#pragma unroll
        for (int kc = 0; kc < 2; kc++)
#pragma unroll
            for (int mi = 0; mi < 4; mi++)
#pragma unroll
                for (int ni = 0; ni < 8; ni++)
                    mma_f16(acc[mi][ni][0], acc[mi][ni][1], acc[mi][ni][2], acc[mi][ni][3],
                            afr[mi * 2 + kc][0], afr[mi * 2 + kc][1],
                            afr[mi * 2 + kc][2], afr[mi * 2 + kc][3],
                            bfr[ni][2 * kc], bfr[ni][2 * kc + 1]);

        // store next stage
        if (it + 1 < NITER) {
            const int nxt = (it + 1) & 1;
            char* ab = dsm + nxt * A_BUF + aoffS;
            *(uint4*)(ab)      = make_uint4(fpack(pa[0].x, pa[0].y), fpack(pa[0].z, pa[0].w),
                                            fpack(pa[1].x, pa[1].y), fpack(pa[1].z, pa[1].w));
            *(uint4*)(ab + 16) = make_uint4(fpack(pa[2].x, pa[2].y), fpack(pa[2].z, pa[2].w),
                                            fpack(pa[3].x, pa[3].y), fpack(pa[3].z, pa[3].w));
            char* bb = dsm + B_OFF + nxt * B_BUF;
#pragma unroll
            for (int jj = 0; jj < 4; jj++) {
                *(uint4*)(bb + boffS[jj]) =
                    make_uint4(fpack(pb[2*jj].x, pb[2*jj].y), fpack(pb[2*jj].z, pb[2*jj].w),
                               fpack(pb[2*jj+1].x, pb[2*jj+1].y), fpack(pb[2*jj+1].z, pb[2*jj+1].w));
            }
        }
        __syncthreads();
    }

    // epilogue
#pragma unroll
    for (int mi = 0; mi < 4; mi++) {
        const int row = by * BM3 + wm * 64 + mi * 16 + gid;
#pragma unroll
        for (int ni = 0; ni < 8; ni++) {
            const int col = bx * BN3 + wn * 64 + ni * 8 + 2 * qid;
            *(float2*)(C + (size_t)row * N + col) =
                make_float2(acc[mi][ni][0], acc[mi][ni][1]);
            *(float2*)(C + (size_t)(row + 8) * N + col) =
                make_float2(acc[mi][ni][2], acc[mi][ni][3]);
        }
    }
}

// ---------------------------------------------------------------------------
// Sparse attention: CTA = 64 tokens x 1 head, smem K/V cache; idx decoded
// inline (int64/int32 sniff: element [0][1] is randint>=1, so second 32-bit
// word == 0 iff the buffer is int64).
// ---------------------------------------------------------------------------
#define TB      64
#define CROWS   96
#define CSLOTS  97
#define CSTRIDE 68

__global__ __launch_bounds__(256)
void sparse_attn(const void* __restrict__ idxraw) {
    __shared__ float Kc[CSLOTS * CSTRIDE];
    __shared__ float Vc[CSLOTS * CSTRIDE];
    __shared__ float qsm[8][CSTRIDE];

    const int b    = blockIdx.x;
    const int h    = blockIdx.y;
    const int tid  = threadIdx.x;
    const int lane = tid & 31;
    const int w    = tid >> 5;

    const int* p32 = (const int*)idxraw;
    const bool is64 = (p32[1] == 0);

    int rowbase = b * TB - 10;
    if (rowbase < 0) rowbase = 0;
    if (rowbase > SS - CROWS) rowbase = SS - CROWS;

    for (int i = tid; i < CSLOTS * 16; i += 256) {
        const int r  = i >> 4;
        const int c4 = (i & 15) * 4;
        const int src = (r < CROWS) ? (rowbase + r) : 0;
        const float4 kv = *(const float4*)(g_k + (size_t)src * DM + h * DKK + c4);
        const float4 vv = *(const float4*)(g_v + (size_t)src * DM + h * DKK + c4);
        *(float4*)(Kc + r * CSTRIDE + c4) = kv;
        *(float4*)(Vc + r * CSTRIDE + c4) = vv;
    }
    __syncthreads();

    for (int i = 0; i < 8; i++) {
        const int t = b * TB + w * 8 + i;
        if (t >= NNG) break;

        __syncwarp();
        *(float2*)(&qsm[w][2 * lane]) =
            *(const float2*)(g_q + (size_t)(t + GG) * DM + h * DKK + 2 * lane);
        __syncwarp();

        const int kidx = is64 ? (int)((const long long*)idxraw)[t * KSEL + lane]
                              : p32[t * KSEL + lane];
        int slot = kidx - rowbase;
        if (kidx == 0) slot = CROWS;
        else if (slot < 0 || slot >= CROWS) slot = -1;

        float dot = 0.0f;
        if (slot >= 0) {
            const float* kr = Kc + slot * CSTRIDE;
            const int rot = slot & 31;
#pragma unroll
            for (int pp = 0; pp < 32; pp++) {
                const int p = (pp + rot) & 31;
                const float2 kv = *(const float2*)(kr + 2 * p);
                const float2 qv = *(const float2*)(&qsm[w][2 * p]);
                dot += kv.x * qv.x + kv.y * qv.y;
            }
        } else {
            const float* kr = g_k + (size_t)kidx * DM + h * DKK;
            const int rot = lane;
#pragma unroll
            for (int pp = 0; pp < 32; pp++) {
                const int p = (pp + rot) & 31;
                const float2 kv = *(const float2*)(kr + 2 * p);
                const float2 qv = *(const float2*)(&qsm[w][2 * p]);
                dot += kv.x * qv.x + kv.y * qv.y;
            }
        }
        const float lg = dot * SCALE;

        float m = lg;
#pragma unroll
        for (int o = 16; o; o >>= 1) m = fmaxf(m, __shfl_xor_sync(0xffffffffu, m, o));
        const float e = __expf(lg - m);
        float sum = e;
#pragma unroll
        for (int o = 16; o; o >>= 1) sum += __shfl_xor_sync(0xffffffffu, sum, o);
        const float prob = e / sum;

        float acc0 = 0.0f, acc1 = 0.0f;
#pragma unroll
        for (int j = 0; j < 32; j++) {
            const float pj = __shfl_sync(0xffffffffu, prob, j);
            const int   sj = __shfl_sync(0xffffffffu, slot, j);
            const int   kj = __shfl_sync(0xffffffffu, kidx, j);
            if (sj >= 0) {
                acc0 = fmaf(pj, Vc[sj * CSTRIDE + lane],      acc0);
                acc1 = fmaf(pj, Vc[sj * CSTRIDE + lane + 32], acc1);
            } else {
                const float* vr = g_v + (size_t)kj * DM + h * DKK;
                acc0 = fmaf(pj, vr[lane],      acc0);
                acc1 = fmaf(pj, vr[lane + 32], acc1);
            }
        }
        float* orow = g_o + (size_t)(t + GG) * DM + h * DKK;
        orow[lane]      = acc0;
        orow[lane + 32] = acc1;
    }
}

// ---------------------------------------------------------------------------
// Global attention, split-K x16: grid (16, 16 heads, 2 tokens), 256 keys/blk.
// ---------------------------------------------------------------------------
__global__ __launch_bounds__(256)
void global_attn_split() {
    __shared__ float lg[256];
    __shared__ float red[256];
    __shared__ float ored[4][DKK];
    __shared__ __align__(16) float qs[DKK];

    const int spl = blockIdx.x;
    const int h   = blockIdx.y;
    const int gi  = blockIdx.z;
    const int srow = gi ? (SS - 1) : 0;
    const int tid = threadIdx.x;
    const int n0  = spl * 256;

    if (tid < DKK) qs[tid] = g_q[(size_t)srow * DM + h * DKK + tid];
    __syncthreads();

    {
        const int n = n0 + tid;
        const float4* kr = (const float4*)(g_k + (size_t)n * DM + h * DKK);
        const float4* qr = (const float4*)qs;
        float dot = 0.0f;
#pragma unroll
        for (int i = 0; i < 16; i++) {
            float4 kv = kr[i], qv = qr[i];
            dot = fmaf(kv.x, qv.x, dot);
            dot = fmaf(kv.y, qv.y, dot);
            dot = fmaf(kv.z, qv.z, dot);
            dot = fmaf(kv.w, qv.w, dot);
        }
        lg[tid] = dot * SCALE;
    }
    red[tid] = lg[tid]; __syncthreads();
    for (int st = 128; st; st >>= 1) {
        if (tid < st) red[tid] = fmaxf(red[tid], red[tid + st]);
        __syncthreads();
    }
    const float m = red[0];
    __syncthreads();

    const float e = __expf(lg[tid] - m);
    lg[tid] = e;
    red[tid] = e; __syncthreads();
    for (int st = 128; st; st >>= 1) {
        if (tid < st) red[tid] += red[tid + st];
        __syncthreads();
    }
    const float s = red[0];
    __syncthreads();

    const int d = tid & 63;
    const int c = tid >> 6;
    float acc = 0.0f;
    const float* vb = g_v + h * DKK + d;
    const int na = c * 64, nb = na + 64;
    for (int nl = na; nl < nb; nl++)
        acc = fmaf(lg[nl], vb[(size_t)(n0 + nl) * DM], acc);
    ored[c][d] = acc;
    __syncthreads();

    const int base = ((gi * HH + h) * NSPL + spl) * 72;
    if (tid < DKK)
        g_gpart[base + tid] = ored[0][tid] + ored[1][tid] + ored[2][tid] + ored[3][tid];
    else if (tid == 64) g_gpart[base + 64] = m;
    else if (tid == 65) g_gpart[base + 65] = s;
}

__global__ __launch_bounds__(64)
void global_attn_combine() {
    const int blk = blockIdx.x;
    const int d   = threadIdx.x;
    const int gi  = blk >> 4;
    const int h   = blk & 15;
    const int srow = gi ? (SS - 1) : 0;

    float M = -1e30f;
#pragma unroll
    for (int i = 0; i < NSPL; i++)
        M = fmaxf(M, g_gpart[(blk * NSPL + i) * 72 + 64]);
    float S = 0.0f, acc = 0.0f;
#pragma unroll
    for (int i = 0; i < NSPL; i++) {
        const int base = (blk * NSPL + i) * 72;
        const float wgt = __expf(g_gpart[base + 64] - M);
        S   += g_gpart[base + 65] * wgt;
        acc += g_gpart[base + d] * wgt;
    }
    g_o[(size_t)srow * DM + h * DKK + d] = acc / S;
}

// ---------------------------------------------------------------------------
extern "C" void kernel_launch(void* const* d_in, const int* in_sizes, int n_in,
                              void* d_out, int out_size) {
    const float* Q  = (const float*)d_in[0];
    const float* Kk = (const float*)d_in[1];
    const float* V  = (const float*)d_in[2];
    const float* Wq = (const float*)d_in[3];
    const float* Wk = (const float*)d_in[4];
    const float* Wv = (const float*)d_in[5];
    const float* Wo = (const float*)d_in[6];
    const void*  idx = (const void*)d_in[7];
    float* out = (float*)d_out;

    float *pq, *pk, *pv, *po;
    cudaGetSymbolAddress((void**)&pq, g_q);
    cudaGetSymbolAddress((void**)&pk, g_k);
    cudaGetSymbolAddress((void**)&pv, g_v);
    cudaGetSymbolAddress((void**)&po, g_o);

    cudaFuncSetAttribute(gemm_f16, cudaFuncAttributeMaxDynamicSharedMemorySize, GSMEM3);

    dim3 qkv_grid(DM / BN3, SS / BM3, 3);   // (4, 32, 3)
    gemm_f16<<<qkv_grid, 256, GSMEM3>>>(Q, Kk, V, Wq, Wk, Wv, pq, pk, pv);

    dim3 sp_grid((NNG + TB - 1) / TB, HH);  // (64, 16)
    sparse_attn<<<sp_grid, 256>>>(idx);

    dim3 gs_grid(NSPL, HH, 2);
    global_attn_split<<<gs_grid, 256>>>();
    global_attn_combine<<<2 * HH, 64>>>();

    dim3 o_grid(DM / BN3, SS / BM3, 1);     // (4, 32, 1)
    gemm_f16<<<o_grid, 256, GSMEM3>>>(po, po, po, Wo, Wo, Wo, out, out, out);
}